// round 2
// baseline (speedup 1.0000x reference)
#include <cuda_runtime.h>
#include <cuda_bf16.h>
#include <math.h>

#define NB 2
#define SS 2048
#define NH 32
#define HS 80
#define HID 2560
#define H3 7680
#define H4 10240
#define ROWS (NB*SS)          // 4096

// ---------------- scratch (static device globals; no allocation) ----------------
__device__ float g_ln[(long)ROWS * HID];          // 40 MB
__device__ float g_qkv[(long)ROWS * H3];          // 120 MB
__device__ float g_scores[(long)NB * NH * SS * SS]; // 1 GiB
__device__ float g_attn[(long)ROWS * HID];        // 40 MB
__device__ float g_fc1[(long)ROWS * H4];          // 160 MB

// ---------------- helpers ----------------
__device__ __forceinline__ float fast_gelu(float x) {
    const float c = 0.7978845608028654f;
    float x3 = x * x * x;
    return 0.5f * x * (1.0f + tanhf(c * (x + 0.044715f * x3)));
}

// 256-thread block reduce; sh must have >= 8 floats
__device__ __forceinline__ float block_reduce_sum(float v, float* sh) {
    #pragma unroll
    for (int o = 16; o > 0; o >>= 1) v += __shfl_xor_sync(0xffffffffu, v, o);
    int wid = threadIdx.x >> 5;
    if ((threadIdx.x & 31) == 0) sh[wid] = v;
    __syncthreads();
    if (threadIdx.x < 32) {
        float t = (threadIdx.x < 8) ? sh[threadIdx.x] : 0.0f;
        #pragma unroll
        for (int o = 4; o > 0; o >>= 1) t += __shfl_xor_sync(0xffffffffu, t, o);
        if (threadIdx.x == 0) sh[0] = t;
    }
    __syncthreads();
    float r = sh[0];
    __syncthreads();
    return r;
}

__device__ __forceinline__ float block_reduce_max(float v, float* sh) {
    #pragma unroll
    for (int o = 16; o > 0; o >>= 1) v = fmaxf(v, __shfl_xor_sync(0xffffffffu, v, o));
    int wid = threadIdx.x >> 5;
    if ((threadIdx.x & 31) == 0) sh[wid] = v;
    __syncthreads();
    if (threadIdx.x < 32) {
        float t = (threadIdx.x < 8) ? sh[threadIdx.x] : -3.4e38f;
        #pragma unroll
        for (int o = 4; o > 0; o >>= 1) t = fmaxf(t, __shfl_xor_sync(0xffffffffu, t, o));
        if (threadIdx.x == 0) sh[0] = t;
    }
    __syncthreads();
    float r = sh[0];
    __syncthreads();
    return r;
}

// ---------------- LayerNorm: one block per row ----------------
__global__ void ln_kernel(const float* __restrict__ x,
                          const float* __restrict__ w,
                          const float* __restrict__ b,
                          float* __restrict__ y) {
    __shared__ float sh[8];
    long row = blockIdx.x;
    const float* xr = x + row * HID;
    float* yr = y + row * HID;
    float vals[10];
    float sum = 0.0f;
    #pragma unroll
    for (int i = 0; i < 10; i++) {
        vals[i] = xr[threadIdx.x + i * 256];
        sum += vals[i];
    }
    float mean = block_reduce_sum(sum, sh) * (1.0f / HID);
    float sq = 0.0f;
    #pragma unroll
    for (int i = 0; i < 10; i++) {
        float d = vals[i] - mean;
        sq += d * d;
    }
    float var = block_reduce_sum(sq, sh) * (1.0f / HID);
    float inv = rsqrtf(var + 1e-5f);
    #pragma unroll
    for (int i = 0; i < 10; i++) {
        int idx = threadIdx.x + i * 256;
        yr[idx] = (vals[i] - mean) * inv * w[idx] + b[idx];
    }
}

// ---------------- generic 128x128x8 SGEMM, batched-strided, epilogues ----------------
// EPI: 0 = C=acc ; 1 = C=acc+bias ; 2 = C=gelu(acc+bias) ; 3 = C += acc+bias
#define BM 128
#define BN 128
#define BKS 8

template<bool TRANS_B, int EPI>
__global__ __launch_bounds__(256)
void gemm_kernel(const float* __restrict__ A, int lda, long sAb, long sAh,
                 const float* __restrict__ B, int ldb, long sBb, long sBh,
                 float* __restrict__ C, int ldc, long sCb, long sCh,
                 int M, int N, int K, int HB,
                 const float* __restrict__ bias) {
    __shared__ float As[BKS][BM + 4];
    __shared__ float Bs[BKS][BN + 4];

    int z = blockIdx.z;
    int zb = z / HB, zh = z % HB;
    A += zb * sAb + zh * sAh;
    B += zb * sBb + zh * sBh;
    C += zb * sCb + zh * sCh;

    int tid = threadIdx.x;
    int tx = tid & 15, ty = tid >> 4;
    int block_m = blockIdx.y * BM;
    int block_n = blockIdx.x * BN;

    float acc[8][8];
    #pragma unroll
    for (int i = 0; i < 8; i++)
        #pragma unroll
        for (int j = 0; j < 8; j++) acc[i][j] = 0.0f;

    int a_row = tid >> 1;
    int a_kc  = (tid & 1) * 4;
    int b_kr  = tid >> 5;            // non-trans B
    int b_nc  = (tid & 31) * 4;
    int bt_n  = tid >> 1;            // trans B
    int bt_kc = (tid & 1) * 4;

    for (int kt = 0; kt < K; kt += BKS) {
        {
            const float* ap = A + (long)(block_m + a_row) * lda + kt + a_kc;
            float4 v = *(const float4*)ap;
            As[a_kc + 0][a_row] = v.x;
            As[a_kc + 1][a_row] = v.y;
            As[a_kc + 2][a_row] = v.z;
            As[a_kc + 3][a_row] = v.w;
        }
        if (!TRANS_B) {
            int n = block_n + b_nc;
            float4 v = make_float4(0.f, 0.f, 0.f, 0.f);
            if (n < N) v = *(const float4*)(B + (long)(kt + b_kr) * ldb + n);
            *(float4*)&Bs[b_kr][b_nc] = v;
        } else {
            int n = block_n + bt_n;
            float4 v = make_float4(0.f, 0.f, 0.f, 0.f);
            if (n < N) v = *(const float4*)(B + (long)n * ldb + kt + bt_kc);
            Bs[bt_kc + 0][bt_n] = v.x;
            Bs[bt_kc + 1][bt_n] = v.y;
            Bs[bt_kc + 2][bt_n] = v.z;
            Bs[bt_kc + 3][bt_n] = v.w;
        }
        __syncthreads();
        #pragma unroll
        for (int k = 0; k < BKS; k++) {
            float a[8], b[8];
            *(float4*)&a[0] = *(const float4*)&As[k][ty * 8];
            *(float4*)&a[4] = *(const float4*)&As[k][ty * 8 + 4];
            *(float4*)&b[0] = *(const float4*)&Bs[k][tx * 8];
            *(float4*)&b[4] = *(const float4*)&Bs[k][tx * 8 + 4];
            #pragma unroll
            for (int i = 0; i < 8; i++)
                #pragma unroll
                for (int j = 0; j < 8; j++)
                    acc[i][j] = fmaf(a[i], b[j], acc[i][j]);
        }
        __syncthreads();
    }

    #pragma unroll
    for (int i = 0; i < 8; i++) {
        int m = block_m + ty * 8 + i;
        if (m >= M) continue;
        #pragma unroll
        for (int j = 0; j < 8; j++) {
            int n = block_n + tx * 8 + j;
            if (n >= N) continue;
            float v = acc[i][j];
            if (EPI >= 1) v += bias[n];
            if (EPI == 2) v = fast_gelu(v);
            float* cp = C + (long)m * ldc + n;
            if (EPI == 3) v += *cp;
            *cp = v;
        }
    }
}

// ---------------- partial RoPE applied in-place to q and k slices of qkv ----------------
__global__ void rope_kernel(float* __restrict__ qkv) {
    int idx = blockIdx.x * blockDim.x + threadIdx.x;
    const int total = NB * SS * NH * 16;
    if (idx >= total) return;
    int p = idx & 15;
    int h = (idx >> 4) & 31;
    int s = (idx >> 9) & (SS - 1);
    int b = idx >> 20;   // 9 + 11 bits
    // inv_freq = 10000^(-p/16)
    float inv = __expf(-(float)p * (9.210340371976184f / 16.0f));
    float angle = (float)s * inv;
    float sn, cs;
    sincosf(angle, &sn, &cs);
    long base = ((long)b * SS + s) * H3 + (long)h * HS;
    float* qp = qkv + base;
    float* kp = qkv + base + HID;
    float q1 = qp[p], q2 = qp[p + 16];
    qp[p]      = q1 * cs - q2 * sn;
    qp[p + 16] = q1 * sn + q2 * cs;
    float k1 = kp[p], k2 = kp[p + 16];
    kp[p]      = k1 * cs - k2 * sn;
    kp[p + 16] = k1 * sn + k2 * cs;
}

// ---------------- causal softmax over score rows (scale applied here) ----------------
__global__ void softmax_kernel(float* __restrict__ scores, float scale) {
    __shared__ float sh[8];
    int q = blockIdx.x;
    long off = ((long)blockIdx.y * SS + q) * SS;
    float* row = scores + off;
    int n = q + 1;
    int tid = threadIdx.x;

    float mx = -3.4e38f;
    for (int k = tid; k < n; k += 256) mx = fmaxf(mx, row[k] * scale);
    float mx_all = block_reduce_max(mx, sh);

    float sum = 0.0f;
    for (int k = tid; k < n; k += 256) {
        float e = __expf(row[k] * scale - mx_all);
        row[k] = e;
        sum += e;
    }
    float sum_all = block_reduce_sum(sum, sh);
    float rinv = 1.0f / sum_all;
    for (int k = tid; k < n; k += 256) row[k] *= rinv;
    for (int k = n + tid; k < SS; k += 256) row[k] = 0.0f;
}

// ---------------- out = src (residual init) ----------------
__global__ void copy_kernel(const float* __restrict__ src, float* __restrict__ dst, long n4) {
    long i = (long)blockIdx.x * blockDim.x + threadIdx.x;
    if (i < n4) ((float4*)dst)[i] = ((const float4*)src)[i];
}

// ---------------- host-side launcher ----------------
static float* sym_addr(const void* symbol) {
    void* p = nullptr;
    cudaGetSymbolAddress(&p, symbol);
    return (float*)p;
}

extern "C" void kernel_launch(void* const* d_in, const int* in_sizes, int n_in,
                              void* d_out, int out_size) {
    const float* hidden   = (const float*)d_in[0];
    const float* ln_w     = (const float*)d_in[1];
    const float* ln_b     = (const float*)d_in[2];
    const float* qkv_w    = (const float*)d_in[3];
    const float* qkv_b    = (const float*)d_in[4];
    const float* out_w    = (const float*)d_in[5];
    const float* out_b    = (const float*)d_in[6];
    const float* fc1_w    = (const float*)d_in[7];
    const float* fc1_b    = (const float*)d_in[8];
    const float* fc2_w    = (const float*)d_in[9];
    const float* fc2_b    = (const float*)d_in[10];
    float* out = (float*)d_out;

    float* ln   = sym_addr(g_ln);
    float* qkv  = sym_addr(g_qkv);
    float* sc   = sym_addr(g_scores);
    float* attn = sym_addr(g_attn);
    float* fc1  = sym_addr(g_fc1);

    // 1. LayerNorm
    ln_kernel<<<ROWS, 256>>>(hidden, ln_w, ln_b, ln);

    // 2. QKV = ln @ Wqkv + b   [4096 x 7680]
    gemm_kernel<false, 1><<<dim3(H3 / BN, ROWS / BM, 1), 256>>>(
        ln, HID, 0, 0, qkv_w, H3, 0, 0, qkv, H3, 0, 0,
        ROWS, H3, HID, 1, qkv_b);

    // 3. RoPE on q,k (in place)
    {
        int total = NB * SS * NH * 16;
        rope_kernel<<<(total + 255) / 256, 256>>>(qkv);
    }

    // 4. scores[bh] = q_bh @ k_bh^T   (batched over 64)
    gemm_kernel<true, 0><<<dim3(SS / BN, SS / BM, NB * NH), 256>>>(
        qkv, H3, (long)SS * H3, HS,
        qkv + HID, H3, (long)SS * H3, HS,
        sc, SS, (long)NH * SS * SS, (long)SS * SS,
        SS, SS, HS, NH, nullptr);

    // 5. causal softmax (with 1/sqrt(80) scale)
    softmax_kernel<<<dim3(SS, NB * NH), 256>>>(sc, 0.11180339887498949f);

    // 6. attn[bh] = P_bh @ v_bh   [2048 x 80] batched
    gemm_kernel<false, 0><<<dim3(1, SS / BM, NB * NH), 256>>>(
        sc, SS, (long)NH * SS * SS, (long)SS * SS,
        qkv + 2 * HID, H3, (long)SS * H3, HS,
        attn, HID, (long)SS * HID, HS,
        SS, HS, SS, NH, nullptr);

    // 7. out = hidden (residual)
    {
        long n4 = (long)ROWS * HID / 4;
        copy_kernel<<<(unsigned)((n4 + 255) / 256), 256>>>(hidden, out, n4);
    }

    // 8. out += attn @ Wo + bo
    gemm_kernel<false, 3><<<dim3(HID / BN, ROWS / BM, 1), 256>>>(
        attn, HID, 0, 0, out_w, HID, 0, 0, out, HID, 0, 0,
        ROWS, HID, HID, 1, out_b);

    // 9. fc1 = gelu(ln @ W1 + b1)   [4096 x 10240]
    gemm_kernel<false, 2><<<dim3(H4 / BN, ROWS / BM, 1), 256>>>(
        ln, HID, 0, 0, fc1_w, H4, 0, 0, fc1, H4, 0, 0,
        ROWS, H4, HID, 1, fc1_b);

    // 10. out += fc1 @ W2 + b2
    gemm_kernel<false, 3><<<dim3(HID / BN, ROWS / BM, 1), 256>>>(
        fc1, H4, 0, 0, fc2_w, HID, 0, 0, out, HID, 0, 0,
        ROWS, HID, H4, 1, fc2_b);
}

// round 6
// speedup vs baseline: 2.3809x; 2.3809x over previous
#include <cuda_runtime.h>
#include <cuda_bf16.h>
#include <math.h>
#include <stdint.h>

#define NB 2
#define SS 2048
#define NH 32
#define HS 80
#define HID 2560
#define H3 7680
#define H4 10240
#define ROWS (NB*SS)          // 4096

// ---------------- scratch (static device globals; no allocation) ----------------
__device__ float g_ln[(long)ROWS * HID];            // 40 MB  (tf32-rounded)
__device__ float g_qkv[(long)ROWS * H3];            // 120 MB
__device__ float g_scores[(long)NB * NH * SS * SS]; // 1 GiB
__device__ float g_attn[(long)ROWS * HID];          // 40 MB  (tf32-rounded)
__device__ float g_fc1[(long)ROWS * H4];            // 160 MB (tf32-rounded)
// transposed (tf32-rounded) weights: WT[n][k] = W[k][n]
__device__ float g_wqkv_t[(long)H3 * HID];
__device__ float g_wout_t[(long)HID * HID];
__device__ float g_w1_t[(long)H4 * HID];
__device__ float g_w2_t[(long)HID * H4];

// ---------------- small helpers ----------------
__device__ __forceinline__ float fast_gelu(float x) {
    const float c = 0.7978845608028654f;
    float x3 = x * x * x;
    return 0.5f * x * (1.0f + tanhf(c * (x + 0.044715f * x3)));
}

__device__ __forceinline__ uint32_t f2tf32(float x) {
    uint32_t r;
    asm("cvt.rna.tf32.f32 %0, %1;" : "=r"(r) : "f"(x));
    return r;
}
__device__ __forceinline__ float round_tf32(float x) {
    return __uint_as_float(f2tf32(x));
}

__device__ __forceinline__ uint32_t smem_u32(const void* p) {
    uint32_t a;
    asm("{ .reg .u64 t; cvta.to.shared.u64 t, %1; cvt.u32.u64 %0, t; }" : "=r"(a) : "l"(p));
    return a;
}

__device__ __forceinline__ void cp16(uint32_t dst, const void* src) {
    asm volatile("cp.async.cg.shared.global [%0], [%1], 16;" :: "r"(dst), "l"(src));
}
#define CP_COMMIT() asm volatile("cp.async.commit_group;" ::: "memory")
#define CP_WAIT1()  asm volatile("cp.async.wait_group 1;" ::: "memory")

__device__ __forceinline__ void mma_tf32(float* d, const uint32_t* a, const uint32_t* b) {
    asm volatile("mma.sync.aligned.m16n8k8.row.col.f32.tf32.tf32.f32 "
        "{%0,%1,%2,%3}, {%4,%5,%6,%7}, {%8,%9}, {%0,%1,%2,%3};"
        : "+f"(d[0]), "+f"(d[1]), "+f"(d[2]), "+f"(d[3])
        : "r"(a[0]), "r"(a[1]), "r"(a[2]), "r"(a[3]), "r"(b[0]), "r"(b[1]));
}

// ---------------- block reduce ----------------
__device__ __forceinline__ float block_reduce_sum(float v, float* sh) {
    #pragma unroll
    for (int o = 16; o > 0; o >>= 1) v += __shfl_xor_sync(0xffffffffu, v, o);
    int wid = threadIdx.x >> 5;
    if ((threadIdx.x & 31) == 0) sh[wid] = v;
    __syncthreads();
    if (threadIdx.x < 32) {
        float t = (threadIdx.x < 8) ? sh[threadIdx.x] : 0.0f;
        #pragma unroll
        for (int o = 4; o > 0; o >>= 1) t += __shfl_xor_sync(0xffffffffu, t, o);
        if (threadIdx.x == 0) sh[0] = t;
    }
    __syncthreads();
    float r = sh[0];
    __syncthreads();
    return r;
}

__device__ __forceinline__ float block_reduce_max(float v, float* sh) {
    #pragma unroll
    for (int o = 16; o > 0; o >>= 1) v = fmaxf(v, __shfl_xor_sync(0xffffffffu, v, o));
    int wid = threadIdx.x >> 5;
    if ((threadIdx.x & 31) == 0) sh[wid] = v;
    __syncthreads();
    if (threadIdx.x < 32) {
        float t = (threadIdx.x < 8) ? sh[threadIdx.x] : -3.4e38f;
        #pragma unroll
        for (int o = 4; o > 0; o >>= 1) t = fmaxf(t, __shfl_xor_sync(0xffffffffu, t, o));
        if (threadIdx.x == 0) sh[0] = t;
    }
    __syncthreads();
    float r = sh[0];
    __syncthreads();
    return r;
}

// ---------------- LayerNorm (output rounded to tf32: feeds tf32 GEMMs only) ----------------
__global__ void ln_kernel(const float* __restrict__ x,
                          const float* __restrict__ w,
                          const float* __restrict__ b,
                          float* __restrict__ y) {
    __shared__ float sh[8];
    long row = blockIdx.x;
    const float* xr = x + row * HID;
    float* yr = y + row * HID;
    float vals[10];
    float sum = 0.0f;
    #pragma unroll
    for (int i = 0; i < 10; i++) { vals[i] = xr[threadIdx.x + i * 256]; sum += vals[i]; }
    float mean = block_reduce_sum(sum, sh) * (1.0f / HID);
    float sq = 0.0f;
    #pragma unroll
    for (int i = 0; i < 10; i++) { float d = vals[i] - mean; sq += d * d; }
    float var = block_reduce_sum(sq, sh) * (1.0f / HID);
    float inv = rsqrtf(var + 1e-5f);
    #pragma unroll
    for (int i = 0; i < 10; i++) {
        int idx = threadIdx.x + i * 256;
        yr[idx] = round_tf32((vals[i] - mean) * inv * w[idx] + b[idx]);
    }
}

// ---------------- weight transpose + tf32 round: WT[n][k] = tf32(W[k][n]) ----------------
__global__ void transpose_tf32_kernel(const float* __restrict__ W, float* __restrict__ WT,
                                      int K, int N) {
    __shared__ float t[32][33];
    int k0 = blockIdx.y * 32, n0 = blockIdx.x * 32;
    int x = threadIdx.x, y = threadIdx.y;   // 32 x 8
    #pragma unroll
    for (int i = 0; i < 32; i += 8)
        t[y + i][x] = W[(long)(k0 + y + i) * N + n0 + x];
    __syncthreads();
    #pragma unroll
    for (int i = 0; i < 32; i += 8)
        WT[(long)(n0 + y + i) * K + k0 + x] = round_tf32(t[x][y + i]);
}

// ================= tf32 mma.sync GEMM: C[M,N] = A[M,K] @ WT[N,K]^T =================
// EPI: 1 = C=acc+bias ; 2 = C=tf32(gelu(acc+bias)) ; 3 = C += acc+bias
#define MSTAGES 3
#define MBK 16
#define APITCH 20
#define STAGE_FLOATS (128 * APITCH)                  // 2560 floats / stage / operand
#define MMA_SMEM (MSTAGES * 2 * STAGE_FLOATS * 4)    // 61440 bytes

template<int EPI>
__global__ __launch_bounds__(256, 2)
void gemm_mma(const float* __restrict__ A, int lda,
              const float* __restrict__ B, int ldb,   // B = W^T [N,K] row-major, tf32-rounded
              float* __restrict__ C, int ldc,
              int K, const float* __restrict__ bias) {
    extern __shared__ float sm[];
    float* As = sm;                                // [MSTAGES][128][APITCH]
    float* Bs = sm + MSTAGES * STAGE_FLOATS;

    int tid = threadIdx.x;
    int wid = tid >> 5, lane = tid & 31;
    int gid = lane >> 2, tig = lane & 3;
    int m_off = (wid >> 2) * 64;
    int n_off = (wid & 3) * 32;

    const float* Ab = A + (long)blockIdx.y * 128 * lda;
    const float* Bb = B + (long)blockIdx.x * 128 * ldb;

    uint32_t as_u32 = smem_u32(As);
    uint32_t bs_u32 = smem_u32(Bs);
    int lr = tid >> 2;            // 0..63
    int lc = (tid & 3) * 4;       // 0,4,8,12

    float acc[4][4][4];
    #pragma unroll
    for (int i = 0; i < 4; i++)
        #pragma unroll
        for (int j = 0; j < 4; j++)
            #pragma unroll
            for (int k = 0; k < 4; k++) acc[i][j][k] = 0.0f;

    int iters = K / MBK;

    // prologue: load stages 0,1
    #pragma unroll
    for (int s = 0; s < 2; s++) {
        const float* ag = Ab + (long)lr * lda + s * MBK + lc;
        const float* bg = Bb + (long)lr * ldb + s * MBK + lc;
        uint32_t ad = as_u32 + (uint32_t)(s * STAGE_FLOATS + lr * APITCH + lc) * 4u;
        uint32_t bd = bs_u32 + (uint32_t)(s * STAGE_FLOATS + lr * APITCH + lc) * 4u;
        cp16(ad, ag);
        cp16(ad + 64u * APITCH * 4u, ag + 64 * lda);
        cp16(bd, bg);
        cp16(bd + 64u * APITCH * 4u, bg + 64 * ldb);
        CP_COMMIT();
    }

    for (int it = 0; it < iters; ++it) {
        int lt = it + 2;
        if (lt < iters) {
            int s = lt % MSTAGES;
            const float* ag = Ab + (long)lr * lda + lt * MBK + lc;
            const float* bg = Bb + (long)lr * ldb + lt * MBK + lc;
            uint32_t ad = as_u32 + (uint32_t)(s * STAGE_FLOATS + lr * APITCH + lc) * 4u;
            uint32_t bd = bs_u32 + (uint32_t)(s * STAGE_FLOATS + lr * APITCH + lc) * 4u;
            cp16(ad, ag);
            cp16(ad + 64u * APITCH * 4u, ag + 64 * lda);
            cp16(bd, bg);
            cp16(bd + 64u * APITCH * 4u, bg + 64 * ldb);
        }
        CP_COMMIT();
        CP_WAIT1();
        __syncthreads();

        const uint32_t* as = (const uint32_t*)(As + (it % MSTAGES) * STAGE_FLOATS);
        const uint32_t* bs = (const uint32_t*)(Bs + (it % MSTAGES) * STAGE_FLOATS);

        #pragma unroll
        for (int kk = 0; kk < MBK; kk += 8) {
            uint32_t af[4][4], bf[4][2];
            #pragma unroll
            for (int mt = 0; mt < 4; mt++) {
                int base = (m_off + mt * 16 + gid) * APITCH + kk + tig;
                af[mt][0] = as[base];
                af[mt][1] = as[base + 8 * APITCH];
                af[mt][2] = as[base + 4];
                af[mt][3] = as[base + 8 * APITCH + 4];
            }
            #pragma unroll
            for (int nt = 0; nt < 4; nt++) {
                int base = (n_off + nt * 8 + gid) * APITCH + kk + tig;
                bf[nt][0] = bs[base];
                bf[nt][1] = bs[base + 4];
            }
            #pragma unroll
            for (int mt = 0; mt < 4; mt++)
                #pragma unroll
                for (int nt = 0; nt < 4; nt++)
                    mma_tf32(acc[mt][nt], af[mt], bf[nt]);
        }
        __syncthreads();
    }

    // epilogue
    #pragma unroll
    for (int mt = 0; mt < 4; mt++) {
        #pragma unroll
        for (int half = 0; half < 2; half++) {
            long m = (long)blockIdx.y * 128 + m_off + mt * 16 + gid + half * 8;
            #pragma unroll
            for (int nt = 0; nt < 4; nt++) {
                int n = blockIdx.x * 128 + n_off + nt * 8 + 2 * tig;
                float v0 = acc[mt][nt][half * 2 + 0] + bias[n];
                float v1 = acc[mt][nt][half * 2 + 1] + bias[n + 1];
                if (EPI == 2) {
                    v0 = round_tf32(fast_gelu(v0));
                    v1 = round_tf32(fast_gelu(v1));
                }
                float* cp = C + m * ldc + n;
                if (EPI == 3) {
                    float2 c = *(float2*)cp;
                    v0 += c.x; v1 += c.y;
                }
                *(float2*)cp = make_float2(v0, v1);
            }
        }
    }
}

// ---------------- SIMT SGEMM (attention: scores, AV) ----------------
#define BM 128
#define BN 128
#define BKS 8

template<bool TRANS_B, bool RND>
__global__ __launch_bounds__(256)
void gemm_simt(const float* __restrict__ A, int lda, long sAb, long sAh,
               const float* __restrict__ B, int ldb, long sBb, long sBh,
               float* __restrict__ C, int ldc, long sCb, long sCh,
               int M, int N, int K, int HB) {
    __shared__ float As[BKS][BM + 4];
    __shared__ float Bs[BKS][BN + 4];

    int z = blockIdx.z;
    int zb = z / HB, zh = z % HB;
    A += zb * sAb + zh * sAh;
    B += zb * sBb + zh * sBh;
    C += zb * sCb + zh * sCh;

    int tid = threadIdx.x;
    int tx = tid & 15, ty = tid >> 4;
    int block_m = blockIdx.y * BM;
    int block_n = blockIdx.x * BN;

    float acc[8][8];
    #pragma unroll
    for (int i = 0; i < 8; i++)
        #pragma unroll
        for (int j = 0; j < 8; j++) acc[i][j] = 0.0f;

    int a_row = tid >> 1;
    int a_kc  = (tid & 1) * 4;
    int b_kr  = tid >> 5;
    int b_nc  = (tid & 31) * 4;
    int bt_n  = tid >> 1;
    int bt_kc = (tid & 1) * 4;

    for (int kt = 0; kt < K; kt += BKS) {
        {
            const float* ap = A + (long)(block_m + a_row) * lda + kt + a_kc;
            float4 v = *(const float4*)ap;
            As[a_kc + 0][a_row] = v.x;
            As[a_kc + 1][a_row] = v.y;
            As[a_kc + 2][a_row] = v.z;
            As[a_kc + 3][a_row] = v.w;
        }
        if (!TRANS_B) {
            int n = block_n + b_nc;
            float4 v = make_float4(0.f, 0.f, 0.f, 0.f);
            if (n < N) v = *(const float4*)(B + (long)(kt + b_kr) * ldb + n);
            *(float4*)&Bs[b_kr][b_nc] = v;
        } else {
            int n = block_n + bt_n;
            float4 v = make_float4(0.f, 0.f, 0.f, 0.f);
            if (n < N) v = *(const float4*)(B + (long)n * ldb + kt + bt_kc);
            Bs[bt_kc + 0][bt_n] = v.x;
            Bs[bt_kc + 1][bt_n] = v.y;
            Bs[bt_kc + 2][bt_n] = v.z;
            Bs[bt_kc + 3][bt_n] = v.w;
        }
        __syncthreads();
        #pragma unroll
        for (int k = 0; k < BKS; k++) {
            float a[8], b[8];
            *(float4*)&a[0] = *(const float4*)&As[k][ty * 8];
            *(float4*)&a[4] = *(const float4*)&As[k][ty * 8 + 4];
            *(float4*)&b[0] = *(const float4*)&Bs[k][tx * 8];
            *(float4*)&b[4] = *(const float4*)&Bs[k][tx * 8 + 4];
            #pragma unroll
            for (int i = 0; i < 8; i++)
                #pragma unroll
                for (int j = 0; j < 8; j++)
                    acc[i][j] = fmaf(a[i], b[j], acc[i][j]);
        }
        __syncthreads();
    }

    #pragma unroll
    for (int i = 0; i < 8; i++) {
        int m = block_m + ty * 8 + i;
        if (m >= M) continue;
        #pragma unroll
        for (int j = 0; j < 8; j++) {
            int n = block_n + tx * 8 + j;
            if (n >= N) continue;
            float v = acc[i][j];
            if (RND) v = round_tf32(v);
            C[(long)m * ldc + n] = v;
        }
    }
}

// ---------------- partial RoPE (in-place on q,k slices of qkv) ----------------
__global__ void rope_kernel(float* __restrict__ qkv) {
    int idx = blockIdx.x * blockDim.x + threadIdx.x;
    const int total = NB * SS * NH * 16;
    if (idx >= total) return;
    int p = idx & 15;
    int h = (idx >> 4) & 31;
    int s = (idx >> 9) & (SS - 1);
    int b = idx >> 20;
    float inv = __expf(-(float)p * (9.210340371976184f / 16.0f));
    float angle = (float)s * inv;
    float sn, cs;
    sincosf(angle, &sn, &cs);
    long base = ((long)b * SS + s) * H3 + (long)h * HS;
    float* qp = qkv + base;
    float* kp = qkv + base + HID;
    float q1 = qp[p], q2 = qp[p + 16];
    qp[p]      = q1 * cs - q2 * sn;
    qp[p + 16] = q1 * sn + q2 * cs;
    float k1 = kp[p], k2 = kp[p + 16];
    kp[p]      = k1 * cs - k2 * sn;
    kp[p + 16] = k1 * sn + k2 * cs;
}

// ---------------- causal softmax ----------------
__global__ void softmax_kernel(float* __restrict__ scores, float scale) {
    __shared__ float sh[8];
    int q = blockIdx.x;
    long off = ((long)blockIdx.y * SS + q) * SS;
    float* row = scores + off;
    int n = q + 1;
    int tid = threadIdx.x;

    float mx = -3.4e38f;
    for (int k = tid; k < n; k += 256) mx = fmaxf(mx, row[k] * scale);
    float mx_all = block_reduce_max(mx, sh);

    float sum = 0.0f;
    for (int k = tid; k < n; k += 256) {
        float e = __expf(row[k] * scale - mx_all);
        row[k] = e;
        sum += e;
    }
    float sum_all = block_reduce_sum(sum, sh);
    float rinv = 1.0f / sum_all;
    for (int k = tid; k < n; k += 256) row[k] *= rinv;
    for (int k = n + tid; k < SS; k += 256) row[k] = 0.0f;
}

// ---------------- residual copy ----------------
__global__ void copy_kernel(const float* __restrict__ src, float* __restrict__ dst, long n4) {
    long i = (long)blockIdx.x * blockDim.x + threadIdx.x;
    if (i < n4) ((float4*)dst)[i] = ((const float4*)src)[i];
}

// ---------------- host-side launcher ----------------
static float* sym_addr(const void* symbol) {
    void* p = nullptr;
    cudaGetSymbolAddress(&p, symbol);
    return (float*)p;
}

extern "C" void kernel_launch(void* const* d_in, const int* in_sizes, int n_in,
                              void* d_out, int out_size) {
    const float* hidden = (const float*)d_in[0];
    const float* ln_w   = (const float*)d_in[1];
    const float* ln_b   = (const float*)d_in[2];
    const float* qkv_w  = (const float*)d_in[3];
    const float* qkv_b  = (const float*)d_in[4];
    const float* out_w  = (const float*)d_in[5];
    const float* out_b  = (const float*)d_in[6];
    const float* fc1_w  = (const float*)d_in[7];
    const float* fc1_b  = (const float*)d_in[8];
    const float* fc2_w  = (const float*)d_in[9];
    const float* fc2_b  = (const float*)d_in[10];
    float* out = (float*)d_out;

    float* ln    = sym_addr(g_ln);
    float* qkv   = sym_addr(g_qkv);
    float* sc    = sym_addr(g_scores);
    float* attn  = sym_addr(g_attn);
    float* fc1   = sym_addr(g_fc1);
    float* wqkvT = sym_addr(g_wqkv_t);
    float* woutT = sym_addr(g_wout_t);
    float* w1T   = sym_addr(g_w1_t);
    float* w2T   = sym_addr(g_w2_t);

    cudaFuncSetAttribute(gemm_mma<1>, cudaFuncAttributeMaxDynamicSharedMemorySize, MMA_SMEM);
    cudaFuncSetAttribute(gemm_mma<2>, cudaFuncAttributeMaxDynamicSharedMemorySize, MMA_SMEM);
    cudaFuncSetAttribute(gemm_mma<3>, cudaFuncAttributeMaxDynamicSharedMemorySize, MMA_SMEM);

    // 0. transpose + tf32-round weights
    {
        dim3 blk(32, 8);
        transpose_tf32_kernel<<<dim3(H3 / 32, HID / 32), blk>>>(qkv_w, wqkvT, HID, H3);
        transpose_tf32_kernel<<<dim3(HID / 32, HID / 32), blk>>>(out_w, woutT, HID, HID);
        transpose_tf32_kernel<<<dim3(H4 / 32, HID / 32), blk>>>(fc1_w, w1T, HID, H4);
        transpose_tf32_kernel<<<dim3(HID / 32, H4 / 32), blk>>>(fc2_w, w2T, H4, HID);
    }

    // 1. LayerNorm (tf32-rounded output)
    ln_kernel<<<ROWS, 256>>>(hidden, ln_w, ln_b, ln);

    // 2. QKV = ln @ Wqkv + b
    gemm_mma<1><<<dim3(H3 / 128, ROWS / 128), 256, MMA_SMEM>>>(
        ln, HID, wqkvT, HID, qkv, H3, HID, qkv_b);

    // 3. RoPE (in place on q,k)
    {
        int total = NB * SS * NH * 16;
        rope_kernel<<<(total + 255) / 256, 256>>>(qkv);
    }

    // 4. scores[bh] = q_bh @ k_bh^T
    gemm_simt<true, false><<<dim3(SS / BN, SS / BM, NB * NH), 256>>>(
        qkv, H3, (long)SS * H3, HS,
        qkv + HID, H3, (long)SS * H3, HS,
        sc, SS, (long)NH * SS * SS, (long)SS * SS,
        SS, SS, HS, NH);

    // 5. causal softmax (scale = 1/sqrt(80))
    softmax_kernel<<<dim3(SS, NB * NH), 256>>>(sc, 0.11180339887498949f);

    // 6. attn[bh] = P_bh @ v_bh  (tf32-rounded: feeds out-proj tf32 GEMM)
    gemm_simt<false, true><<<dim3(1, SS / BM, NB * NH), 256>>>(
        sc, SS, (long)NH * SS * SS, (long)SS * SS,
        qkv + 2 * HID, H3, (long)SS * H3, HS,
        attn, HID, (long)SS * HID, HS,
        SS, HS, SS, NH);

    // 7. out = hidden (residual)
    {
        long n4 = (long)ROWS * HID / 4;
        copy_kernel<<<(unsigned)((n4 + 255) / 256), 256>>>(hidden, out, n4);
    }

    // 8. out += attn @ Wo + bo
    gemm_mma<3><<<dim3(HID / 128, ROWS / 128), 256, MMA_SMEM>>>(
        attn, HID, woutT, HID, out, HID, HID, out_b);

    // 9. fc1 = tf32(gelu(ln @ W1 + b1))
    gemm_mma<2><<<dim3(H4 / 128, ROWS / 128), 256, MMA_SMEM>>>(
        ln, HID, w1T, HID, fc1, H4, HID, fc1_b);

    // 10. out += fc1 @ W2 + b2
    gemm_mma<3><<<dim3(HID / 128, ROWS / 128), 256, MMA_SMEM>>>(
        fc1, H4, w2T, H4, out, HID, H4, fc2_b);
}

// round 7
// speedup vs baseline: 3.7394x; 1.5706x over previous
#include <cuda_runtime.h>
#include <cuda_bf16.h>
#include <math.h>
#include <stdint.h>

#define NB 2
#define SS 2048
#define NH 32
#define HS 80
#define HID 2560
#define H3 7680
#define H4 10240
#define ROWS (NB*SS)          // 4096

// ---------------- scratch (static device globals; no allocation) ----------------
__device__ float g_ln[(long)ROWS * HID];            // tf32-rounded
__device__ float g_qkv[(long)ROWS * H3];            // tf32-rounded after rope
__device__ float g_attn[(long)ROWS * HID];          // tf32-rounded
__device__ float g_fc1[(long)ROWS * H4];            // tf32-rounded
// transposed (tf32-rounded) weights: WT[n][k] = W[k][n]
__device__ float g_wqkv_t[(long)H3 * HID];
__device__ float g_wout_t[(long)HID * HID];
__device__ float g_w1_t[(long)H4 * HID];
__device__ float g_w2_t[(long)HID * H4];

// ---------------- small helpers ----------------
__device__ __forceinline__ float fast_gelu(float x) {
    const float c = 0.7978845608028654f;
    float x3 = x * x * x;
    return 0.5f * x * (1.0f + tanhf(c * (x + 0.044715f * x3)));
}

__device__ __forceinline__ uint32_t f2tf32(float x) {
    uint32_t r;
    asm("cvt.rna.tf32.f32 %0, %1;" : "=r"(r) : "f"(x));
    return r;
}
__device__ __forceinline__ float round_tf32(float x) {
    return __uint_as_float(f2tf32(x));
}

__device__ __forceinline__ uint32_t smem_u32(const void* p) {
    uint32_t a;
    asm("{ .reg .u64 t; cvta.to.shared.u64 t, %1; cvt.u32.u64 %0, t; }" : "=r"(a) : "l"(p));
    return a;
}

__device__ __forceinline__ void cp16(uint32_t dst, const void* src) {
    asm volatile("cp.async.cg.shared.global [%0], [%1], 16;" :: "r"(dst), "l"(src));
}
#define CP_COMMIT() asm volatile("cp.async.commit_group;" ::: "memory")
#define CP_WAIT1()  asm volatile("cp.async.wait_group 1;" ::: "memory")

__device__ __forceinline__ void mma_tf32(float* d, const uint32_t* a, const uint32_t* b) {
    asm volatile("mma.sync.aligned.m16n8k8.row.col.f32.tf32.tf32.f32 "
        "{%0,%1,%2,%3}, {%4,%5,%6,%7}, {%8,%9}, {%0,%1,%2,%3};"
        : "+f"(d[0]), "+f"(d[1]), "+f"(d[2]), "+f"(d[3])
        : "r"(a[0]), "r"(a[1]), "r"(a[2]), "r"(a[3]), "r"(b[0]), "r"(b[1]));
}

// ---------------- block reduce ----------------
__device__ __forceinline__ float block_reduce_sum(float v, float* sh) {
    #pragma unroll
    for (int o = 16; o > 0; o >>= 1) v += __shfl_xor_sync(0xffffffffu, v, o);
    int wid = threadIdx.x >> 5;
    if ((threadIdx.x & 31) == 0) sh[wid] = v;
    __syncthreads();
    if (threadIdx.x < 32) {
        float t = (threadIdx.x < 8) ? sh[threadIdx.x] : 0.0f;
        #pragma unroll
        for (int o = 4; o > 0; o >>= 1) t += __shfl_xor_sync(0xffffffffu, t, o);
        if (threadIdx.x == 0) sh[0] = t;
    }
    __syncthreads();
    float r = sh[0];
    __syncthreads();
    return r;
}

// ---------------- LayerNorm (tf32-rounded output) ----------------
__global__ void ln_kernel(const float* __restrict__ x,
                          const float* __restrict__ w,
                          const float* __restrict__ b,
                          float* __restrict__ y) {
    __shared__ float sh[8];
    long row = blockIdx.x;
    const float* xr = x + row * HID;
    float* yr = y + row * HID;
    float vals[10];
    float sum = 0.0f;
    #pragma unroll
    for (int i = 0; i < 10; i++) { vals[i] = xr[threadIdx.x + i * 256]; sum += vals[i]; }
    float mean = block_reduce_sum(sum, sh) * (1.0f / HID);
    float sq = 0.0f;
    #pragma unroll
    for (int i = 0; i < 10; i++) { float d = vals[i] - mean; sq += d * d; }
    float var = block_reduce_sum(sq, sh) * (1.0f / HID);
    float inv = rsqrtf(var + 1e-5f);
    #pragma unroll
    for (int i = 0; i < 10; i++) {
        int idx = threadIdx.x + i * 256;
        yr[idx] = round_tf32((vals[i] - mean) * inv * w[idx] + b[idx]);
    }
}

// ---------------- weight transpose + tf32 round: WT[n][k] = tf32(W[k][n]) ----------------
__global__ void transpose_tf32_kernel(const float* __restrict__ W, float* __restrict__ WT,
                                      int K, int N) {
    __shared__ float t[32][33];
    int k0 = blockIdx.y * 32, n0 = blockIdx.x * 32;
    int x = threadIdx.x, y = threadIdx.y;   // 32 x 8
    #pragma unroll
    for (int i = 0; i < 32; i += 8)
        t[y + i][x] = W[(long)(k0 + y + i) * N + n0 + x];
    __syncthreads();
    #pragma unroll
    for (int i = 0; i < 32; i += 8)
        WT[(long)(n0 + y + i) * K + k0 + x] = round_tf32(t[x][y + i]);
}

// ================= tf32 mma.sync GEMM: C[M,N] = A[M,K] @ WT[N,K]^T =================
// EPI: 1 = C=tf32(acc+bias) ; 2 = C=tf32(gelu(acc+bias)) ; 3 = C += acc+bias
#define MSTAGES 3
#define MBK 16
#define APITCH 20
#define STAGE_FLOATS (128 * APITCH)
#define MMA_SMEM (MSTAGES * 2 * STAGE_FLOATS * 4)    // 61440 bytes

template<int EPI>
__global__ __launch_bounds__(256, 2)
void gemm_mma(const float* __restrict__ A, int lda,
              const float* __restrict__ B, int ldb,   // B = W^T [N,K] row-major, tf32-rounded
              float* __restrict__ C, int ldc,
              int K, const float* __restrict__ bias) {
    extern __shared__ float sm[];
    float* As = sm;
    float* Bs = sm + MSTAGES * STAGE_FLOATS;

    int tid = threadIdx.x;
    int wid = tid >> 5, lane = tid & 31;
    int gid = lane >> 2, tig = lane & 3;
    int m_off = (wid >> 2) * 64;
    int n_off = (wid & 3) * 32;

    const float* Ab = A + (long)blockIdx.y * 128 * lda;
    const float* Bb = B + (long)blockIdx.x * 128 * ldb;

    uint32_t as_u32 = smem_u32(As);
    uint32_t bs_u32 = smem_u32(Bs);
    int lr = tid >> 2;
    int lc = (tid & 3) * 4;

    float acc[4][4][4];
    #pragma unroll
    for (int i = 0; i < 4; i++)
        #pragma unroll
        for (int j = 0; j < 4; j++)
            #pragma unroll
            for (int k = 0; k < 4; k++) acc[i][j][k] = 0.0f;

    int iters = K / MBK;

    #pragma unroll
    for (int s = 0; s < 2; s++) {
        const float* ag = Ab + (long)lr * lda + s * MBK + lc;
        const float* bg = Bb + (long)lr * ldb + s * MBK + lc;
        uint32_t ad = as_u32 + (uint32_t)(s * STAGE_FLOATS + lr * APITCH + lc) * 4u;
        uint32_t bd = bs_u32 + (uint32_t)(s * STAGE_FLOATS + lr * APITCH + lc) * 4u;
        cp16(ad, ag);
        cp16(ad + 64u * APITCH * 4u, ag + 64 * lda);
        cp16(bd, bg);
        cp16(bd + 64u * APITCH * 4u, bg + 64 * ldb);
        CP_COMMIT();
    }

    for (int it = 0; it < iters; ++it) {
        int lt = it + 2;
        if (lt < iters) {
            int s = lt % MSTAGES;
            const float* ag = Ab + (long)lr * lda + lt * MBK + lc;
            const float* bg = Bb + (long)lr * ldb + lt * MBK + lc;
            uint32_t ad = as_u32 + (uint32_t)(s * STAGE_FLOATS + lr * APITCH + lc) * 4u;
            uint32_t bd = bs_u32 + (uint32_t)(s * STAGE_FLOATS + lr * APITCH + lc) * 4u;
            cp16(ad, ag);
            cp16(ad + 64u * APITCH * 4u, ag + 64 * lda);
            cp16(bd, bg);
            cp16(bd + 64u * APITCH * 4u, bg + 64 * ldb);
        }
        CP_COMMIT();
        CP_WAIT1();
        __syncthreads();

        const uint32_t* as = (const uint32_t*)(As + (it % MSTAGES) * STAGE_FLOATS);
        const uint32_t* bs = (const uint32_t*)(Bs + (it % MSTAGES) * STAGE_FLOATS);

        #pragma unroll
        for (int kk = 0; kk < MBK; kk += 8) {
            uint32_t af[4][4], bf[4][2];
            #pragma unroll
            for (int mt = 0; mt < 4; mt++) {
                int base = (m_off + mt * 16 + gid) * APITCH + kk + tig;
                af[mt][0] = as[base];
                af[mt][1] = as[base + 8 * APITCH];
                af[mt][2] = as[base + 4];
                af[mt][3] = as[base + 8 * APITCH + 4];
            }
            #pragma unroll
            for (int nt = 0; nt < 4; nt++) {
                int base = (n_off + nt * 8 + gid) * APITCH + kk + tig;
                bf[nt][0] = bs[base];
                bf[nt][1] = bs[base + 4];
            }
            #pragma unroll
            for (int mt = 0; mt < 4; mt++)
                #pragma unroll
                for (int nt = 0; nt < 4; nt++)
                    mma_tf32(acc[mt][nt], af[mt], bf[nt]);
        }
        __syncthreads();
    }

    #pragma unroll
    for (int mt = 0; mt < 4; mt++) {
        #pragma unroll
        for (int half = 0; half < 2; half++) {
            long m = (long)blockIdx.y * 128 + m_off + mt * 16 + gid + half * 8;
            #pragma unroll
            for (int nt = 0; nt < 4; nt++) {
                int n = blockIdx.x * 128 + n_off + nt * 8 + 2 * tig;
                float v0 = acc[mt][nt][half * 2 + 0] + bias[n];
                float v1 = acc[mt][nt][half * 2 + 1] + bias[n + 1];
                if (EPI == 1) { v0 = round_tf32(v0); v1 = round_tf32(v1); }
                if (EPI == 2) {
                    v0 = round_tf32(fast_gelu(v0));
                    v1 = round_tf32(fast_gelu(v1));
                }
                float* cp = C + m * ldc + n;
                if (EPI == 3) {
                    float2 c = *(float2*)cp;
                    v0 += c.x; v1 += c.y;
                }
                *(float2*)cp = make_float2(v0, v1);
            }
        }
    }
}

// ---------------- partial RoPE (in-place, tf32-rounded writes) ----------------
__global__ void rope_kernel(float* __restrict__ qkv) {
    int idx = blockIdx.x * blockDim.x + threadIdx.x;
    const int total = NB * SS * NH * 16;
    if (idx >= total) return;
    int p = idx & 15;
    int h = (idx >> 4) & 31;
    int s = (idx >> 9) & (SS - 1);
    int b = idx >> 20;
    float inv = __expf(-(float)p * (9.210340371976184f / 16.0f));
    float angle = (float)s * inv;
    float sn, cs;
    sincosf(angle, &sn, &cs);
    long base = ((long)b * SS + s) * H3 + (long)h * HS;
    float* qp = qkv + base;
    float* kp = qkv + base + HID;
    float q1 = qp[p], q2 = qp[p + 16];
    qp[p]      = round_tf32(q1 * cs - q2 * sn);
    qp[p + 16] = round_tf32(q1 * sn + q2 * cs);
    float k1 = kp[p], k2 = kp[p + 16];
    kp[p]      = round_tf32(k1 * cs - k2 * sn);
    kp[p + 16] = round_tf32(k1 * sn + k2 * cs);
}

// ================= flash attention (tf32 mma, online softmax) =================
// grid: (SS/128, NB*NH), 256 threads (8 warps, warp = 16 q-rows)
#define FBQ 128
#define FBK 64
#define KVP 84
#define PP  68
#define FLASH_SMEM ((4 * FBK * KVP + FBQ * PP) * 4)   // 120832 bytes

__global__ __launch_bounds__(256, 1)
void flash_kernel(const float* __restrict__ qkv, float* __restrict__ attn) {
    extern __shared__ float fs[];
    float* Ks = fs;                        // [2][FBK][KVP]
    float* Vs = fs + 2 * FBK * KVP;        // [2][FBK][KVP]
    float* Ps = fs + 4 * FBK * KVP;        // [FBQ][PP] (warp-private rows)

    int tid = threadIdx.x, wid = tid >> 5, lane = tid & 31;
    int gid = lane >> 2, tig = lane & 3;
    int q0 = blockIdx.x * FBQ;
    int b = blockIdx.y >> 5, h = blockIdx.y & 31;
    int m0 = wid * 16;

    const float* qbase = qkv + (long)b * SS * H3 + (long)h * HS;
    const float* kbase = qbase + HID;
    const float* vbase = qbase + 2 * HID;

    // Q fragments (pre-rounded tf32 in gmem)
    uint32_t qf[10][4];
    {
        const float* q0p = qbase + (long)(q0 + m0 + gid) * H3;
        const float* q1p = qbase + (long)(q0 + m0 + gid + 8) * H3;
        #pragma unroll
        for (int kk = 0; kk < 10; kk++) {
            qf[kk][0] = __float_as_uint(__ldg(q0p + kk * 8 + tig));
            qf[kk][1] = __float_as_uint(__ldg(q1p + kk * 8 + tig));
            qf[kk][2] = __float_as_uint(__ldg(q0p + kk * 8 + tig + 4));
            qf[kk][3] = __float_as_uint(__ldg(q1p + kk * 8 + tig + 4));
        }
    }

    float oacc[10][4];
    #pragma unroll
    for (int i = 0; i < 10; i++)
        #pragma unroll
        for (int j = 0; j < 4; j++) oacc[i][j] = 0.0f;
    float mrow0 = -1e30f, mrow1 = -1e30f, lrow0 = 0.0f, lrow1 = 0.0f;

    int ntiles = q0 / FBK + 2;
    uint32_t ks_u = smem_u32(Ks), vs_u = smem_u32(Vs);

    // prologue: tile 0 -> stage 0
    {
        #pragma unroll
        for (int i = 0; i < 5; i++) {
            int c = tid + i * 256;
            int r = c / 20, c16 = c % 20;
            uint32_t off = (uint32_t)(r * KVP + c16 * 4) * 4u;
            cp16(ks_u + off, kbase + (long)r * H3 + c16 * 4);
            cp16(vs_u + off, vbase + (long)r * H3 + c16 * 4);
        }
        CP_COMMIT();
    }

    const float scale = 0.11180339887498949f;
    int row0 = q0 + m0 + gid;
    int row1 = row0 + 8;

    for (int t = 0; t < ntiles; ++t) {
        int stage = t & 1;
        __syncthreads();   // all warps done reading stage (t+1)&1 from iter t-1
        if (t + 1 < ntiles) {
            int kv1 = (t + 1) * FBK;
            int st1 = (t + 1) & 1;
            #pragma unroll
            for (int i = 0; i < 5; i++) {
                int c = tid + i * 256;
                int r = c / 20, c16 = c % 20;
                uint32_t off = (uint32_t)((st1 * FBK + r) * KVP + c16 * 4) * 4u;
                cp16(ks_u + off, kbase + (long)(kv1 + r) * H3 + c16 * 4);
                cp16(vs_u + off, vbase + (long)(kv1 + r) * H3 + c16 * 4);
            }
        }
        CP_COMMIT();
        CP_WAIT1();        // stage `stage` (tile t) resident
        __syncthreads();

        // ---- S = Q @ K^T  (warp: 16 x 64) ----
        float sacc[8][4];
        #pragma unroll
        for (int i = 0; i < 8; i++)
            #pragma unroll
            for (int j = 0; j < 4; j++) sacc[i][j] = 0.0f;

        const uint32_t* kt = (const uint32_t*)(Ks + stage * FBK * KVP);
        #pragma unroll
        for (int nt = 0; nt < 8; nt++) {
            int rb = (nt * 8 + gid) * KVP + tig;
            #pragma unroll
            for (int kk = 0; kk < 10; kk++) {
                uint32_t bf[2];
                bf[0] = kt[rb + kk * 8];
                bf[1] = kt[rb + kk * 8 + 4];
                mma_tf32(sacc[nt], qf[kk], bf);
            }
        }

        // ---- scale + causal mask ----
        int kv0 = t * FBK;
        bool need_mask = (t >= ntiles - 2);
        #pragma unroll
        for (int nt = 0; nt < 8; nt++) {
            int c0 = kv0 + nt * 8 + 2 * tig;
            #pragma unroll
            for (int j = 0; j < 4; j++) sacc[nt][j] *= scale;
            if (need_mask) {
                if (c0 > row0)     sacc[nt][0] = -1e30f;
                if (c0 + 1 > row0) sacc[nt][1] = -1e30f;
                if (c0 > row1)     sacc[nt][2] = -1e30f;
                if (c0 + 1 > row1) sacc[nt][3] = -1e30f;
            }
        }

        // ---- online softmax ----
        float rm0 = -1e30f, rm1 = -1e30f;
        #pragma unroll
        for (int nt = 0; nt < 8; nt++) {
            rm0 = fmaxf(rm0, fmaxf(sacc[nt][0], sacc[nt][1]));
            rm1 = fmaxf(rm1, fmaxf(sacc[nt][2], sacc[nt][3]));
        }
        rm0 = fmaxf(rm0, __shfl_xor_sync(0xffffffffu, rm0, 1));
        rm0 = fmaxf(rm0, __shfl_xor_sync(0xffffffffu, rm0, 2));
        rm1 = fmaxf(rm1, __shfl_xor_sync(0xffffffffu, rm1, 1));
        rm1 = fmaxf(rm1, __shfl_xor_sync(0xffffffffu, rm1, 2));
        float mn0 = fmaxf(mrow0, rm0);
        float mn1 = fmaxf(mrow1, rm1);

        float rs0 = 0.0f, rs1 = 0.0f;
        float* pr0 = Ps + (m0 + gid) * PP;
        float* pr1 = Ps + (m0 + gid + 8) * PP;
        #pragma unroll
        for (int nt = 0; nt < 8; nt++) {
            float p0 = __expf(sacc[nt][0] - mn0);
            float p1 = __expf(sacc[nt][1] - mn0);
            float p2 = __expf(sacc[nt][2] - mn1);
            float p3 = __expf(sacc[nt][3] - mn1);
            rs0 += p0 + p1;
            rs1 += p2 + p3;
            int cc = nt * 8 + 2 * tig;
            *(float2*)(pr0 + cc) = make_float2(round_tf32(p0), round_tf32(p1));
            *(float2*)(pr1 + cc) = make_float2(round_tf32(p2), round_tf32(p3));
        }
        rs0 += __shfl_xor_sync(0xffffffffu, rs0, 1);
        rs0 += __shfl_xor_sync(0xffffffffu, rs0, 2);
        rs1 += __shfl_xor_sync(0xffffffffu, rs1, 1);
        rs1 += __shfl_xor_sync(0xffffffffu, rs1, 2);

        float a0 = __expf(mrow0 - mn0);
        float a1 = __expf(mrow1 - mn1);
        lrow0 = lrow0 * a0 + rs0;
        lrow1 = lrow1 * a1 + rs1;
        mrow0 = mn0; mrow1 = mn1;
        #pragma unroll
        for (int nt = 0; nt < 10; nt++) {
            oacc[nt][0] *= a0; oacc[nt][1] *= a0;
            oacc[nt][2] *= a1; oacc[nt][3] *= a1;
        }

        // ---- O += P @ V  (P warp-private rows, no block sync needed) ----
        __syncwarp();
        const uint32_t* pw = (const uint32_t*)Ps;
        const uint32_t* vt = (const uint32_t*)(Vs + stage * FBK * KVP);
        #pragma unroll
        for (int kk = 0; kk < 8; kk++) {
            uint32_t af[4];
            int pb = (m0 + gid) * PP + kk * 8 + tig;
            af[0] = pw[pb];
            af[1] = pw[pb + 8 * PP];
            af[2] = pw[pb + 4];
            af[3] = pw[pb + 8 * PP + 4];
            #pragma unroll
            for (int nt = 0; nt < 10; nt++) {
                uint32_t bf[2];
                int vb = (kk * 8 + tig) * KVP + nt * 8 + gid;
                bf[0] = vt[vb];
                bf[1] = vt[vb + 4 * KVP];
                mma_tf32(oacc[nt], af, bf);
            }
        }
    }

    // ---- epilogue: O /= l, round, store ----
    float inv0 = 1.0f / lrow0;
    float inv1 = 1.0f / lrow1;
    float* o0 = attn + ((long)b * SS + row0) * HID + h * HS;
    float* o1 = attn + ((long)b * SS + row1) * HID + h * HS;
    #pragma unroll
    for (int nt = 0; nt < 10; nt++) {
        int cc = nt * 8 + 2 * tig;
        *(float2*)(o0 + cc) = make_float2(round_tf32(oacc[nt][0] * inv0),
                                          round_tf32(oacc[nt][1] * inv0));
        *(float2*)(o1 + cc) = make_float2(round_tf32(oacc[nt][2] * inv1),
                                          round_tf32(oacc[nt][3] * inv1));
    }
}

// ---------------- residual copy ----------------
__global__ void copy_kernel(const float* __restrict__ src, float* __restrict__ dst, long n4) {
    long i = (long)blockIdx.x * blockDim.x + threadIdx.x;
    if (i < n4) ((float4*)dst)[i] = ((const float4*)src)[i];
}

// ---------------- host-side launcher ----------------
static float* sym_addr(const void* symbol) {
    void* p = nullptr;
    cudaGetSymbolAddress(&p, symbol);
    return (float*)p;
}

extern "C" void kernel_launch(void* const* d_in, const int* in_sizes, int n_in,
                              void* d_out, int out_size) {
    const float* hidden = (const float*)d_in[0];
    const float* ln_w   = (const float*)d_in[1];
    const float* ln_b   = (const float*)d_in[2];
    const float* qkv_w  = (const float*)d_in[3];
    const float* qkv_b  = (const float*)d_in[4];
    const float* out_w  = (const float*)d_in[5];
    const float* out_b  = (const float*)d_in[6];
    const float* fc1_w  = (const float*)d_in[7];
    const float* fc1_b  = (const float*)d_in[8];
    const float* fc2_w  = (const float*)d_in[9];
    const float* fc2_b  = (const float*)d_in[10];
    float* out = (float*)d_out;

    float* ln    = sym_addr(g_ln);
    float* qkv   = sym_addr(g_qkv);
    float* attn  = sym_addr(g_attn);
    float* fc1   = sym_addr(g_fc1);
    float* wqkvT = sym_addr(g_wqkv_t);
    float* woutT = sym_addr(g_wout_t);
    float* w1T   = sym_addr(g_w1_t);
    float* w2T   = sym_addr(g_w2_t);

    cudaFuncSetAttribute(gemm_mma<1>, cudaFuncAttributeMaxDynamicSharedMemorySize, MMA_SMEM);
    cudaFuncSetAttribute(gemm_mma<2>, cudaFuncAttributeMaxDynamicSharedMemorySize, MMA_SMEM);
    cudaFuncSetAttribute(gemm_mma<3>, cudaFuncAttributeMaxDynamicSharedMemorySize, MMA_SMEM);
    cudaFuncSetAttribute(flash_kernel, cudaFuncAttributeMaxDynamicSharedMemorySize, FLASH_SMEM);

    // 0. transpose + tf32-round weights
    {
        dim3 blk(32, 8);
        transpose_tf32_kernel<<<dim3(H3 / 32, HID / 32), blk>>>(qkv_w, wqkvT, HID, H3);
        transpose_tf32_kernel<<<dim3(HID / 32, HID / 32), blk>>>(out_w, woutT, HID, HID);
        transpose_tf32_kernel<<<dim3(H4 / 32, HID / 32), blk>>>(fc1_w, w1T, HID, H4);
        transpose_tf32_kernel<<<dim3(HID / 32, H4 / 32), blk>>>(fc2_w, w2T, H4, HID);
    }

    // 1. LayerNorm (tf32-rounded)
    ln_kernel<<<ROWS, 256>>>(hidden, ln_w, ln_b, ln);

    // 2. QKV = tf32(ln @ Wqkv + b)
    gemm_mma<1><<<dim3(H3 / 128, ROWS / 128), 256, MMA_SMEM>>>(
        ln, HID, wqkvT, HID, qkv, H3, HID, qkv_b);

    // 3. RoPE (in place, rounded)
    {
        int total = NB * SS * NH * 16;
        rope_kernel<<<(total + 255) / 256, 256>>>(qkv);
    }

    // 4-6. fused flash attention -> attn (tf32-rounded)
    flash_kernel<<<dim3(SS / FBQ, NB * NH), 256, FLASH_SMEM>>>(qkv, attn);

    // 7. out = hidden (residual)
    {
        long n4 = (long)ROWS * HID / 4;
        copy_kernel<<<(unsigned)((n4 + 255) / 256), 256>>>(hidden, out, n4);
    }

    // 8. out += attn @ Wo + bo
    gemm_mma<3><<<dim3(HID / 128, ROWS / 128), 256, MMA_SMEM>>>(
        attn, HID, woutT, HID, out, HID, HID, out_b);

    // 9. fc1 = tf32(gelu(ln @ W1 + b1))
    gemm_mma<2><<<dim3(H4 / 128, ROWS / 128), 256, MMA_SMEM>>>(
        ln, HID, w1T, HID, fc1, H4, HID, fc1_b);

    // 10. out += fc1 @ W2 + b2
    gemm_mma<3><<<dim3(HID / 128, ROWS / 128), 256, MMA_SMEM>>>(
        fc1, H4, w2T, H4, out, HID, H4, fc2_b);
}

// round 8
// speedup vs baseline: 7.4713x; 1.9980x over previous
#include <cuda_runtime.h>
#include <cuda_fp16.h>
#include <math.h>
#include <stdint.h>

#define NB 2
#define SS 2048
#define NH 32
#define HS 80
#define HID 2560
#define H3 7680
#define H4 10240
#define ROWS (NB*SS)          // 4096

// ---------------- scratch (static device globals; no allocation) ----------------
__device__ __half g_ln[(long)ROWS * HID];
__device__ __half g_qkv[(long)ROWS * H3];
__device__ __half g_attn[(long)ROWS * HID];
__device__ __half g_fc1[(long)ROWS * H4];
// transposed fp16 weights: WT[n][k] = half(W[k][n])
__device__ __half g_wqkv_t[(long)H3 * HID];
__device__ __half g_wout_t[(long)HID * HID];
__device__ __half g_w1_t[(long)H4 * HID];
__device__ __half g_w2_t[(long)HID * H4];

// ---------------- small helpers ----------------
__device__ __forceinline__ float fast_gelu(float x) {
    const float c = 0.7978845608028654f;
    float x3 = x * x * x;
    return 0.5f * x * (1.0f + tanhf(c * (x + 0.044715f * x3)));
}

__device__ __forceinline__ uint32_t smem_u32(const void* p) {
    uint32_t a;
    asm("{ .reg .u64 t; cvta.to.shared.u64 t, %1; cvt.u32.u64 %0, t; }" : "=r"(a) : "l"(p));
    return a;
}

__device__ __forceinline__ void cp16(uint32_t dst, const void* src) {
    asm volatile("cp.async.cg.shared.global [%0], [%1], 16;" :: "r"(dst), "l"(src));
}
#define CP_COMMIT() asm volatile("cp.async.commit_group;" ::: "memory")
#define CP_WAIT1()  asm volatile("cp.async.wait_group 1;" ::: "memory")

__device__ __forceinline__ void mma_f16(float* d, const uint32_t* a, uint32_t b0, uint32_t b1) {
    asm volatile("mma.sync.aligned.m16n8k16.row.col.f32.f16.f16.f32 "
        "{%0,%1,%2,%3}, {%4,%5,%6,%7}, {%8,%9}, {%0,%1,%2,%3};"
        : "+f"(d[0]), "+f"(d[1]), "+f"(d[2]), "+f"(d[3])
        : "r"(a[0]), "r"(a[1]), "r"(a[2]), "r"(a[3]), "r"(b0), "r"(b1));
}

__device__ __forceinline__ void ldsm_x4(uint32_t* r, uint32_t addr) {
    asm volatile("ldmatrix.sync.aligned.m8n8.x4.shared.b16 {%0,%1,%2,%3}, [%4];"
        : "=r"(r[0]), "=r"(r[1]), "=r"(r[2]), "=r"(r[3]) : "r"(addr));
}
__device__ __forceinline__ void ldsm_x2_trans(uint32_t& r0, uint32_t& r1, uint32_t addr) {
    asm volatile("ldmatrix.sync.aligned.m8n8.x2.trans.shared.b16 {%0,%1}, [%2];"
        : "=r"(r0), "=r"(r1) : "r"(addr));
}

__device__ __forceinline__ uint32_t packh2(float a, float b) {
    __half2 h = __floats2half2_rn(a, b);
    return *reinterpret_cast<uint32_t*>(&h);
}

// ---------------- block reduce ----------------
__device__ __forceinline__ float block_reduce_sum(float v, float* sh) {
    #pragma unroll
    for (int o = 16; o > 0; o >>= 1) v += __shfl_xor_sync(0xffffffffu, v, o);
    int wid = threadIdx.x >> 5;
    if ((threadIdx.x & 31) == 0) sh[wid] = v;
    __syncthreads();
    if (threadIdx.x < 32) {
        float t = (threadIdx.x < 8) ? sh[threadIdx.x] : 0.0f;
        #pragma unroll
        for (int o = 4; o > 0; o >>= 1) t += __shfl_xor_sync(0xffffffffu, t, o);
        if (threadIdx.x == 0) sh[0] = t;
    }
    __syncthreads();
    float r = sh[0];
    __syncthreads();
    return r;
}

// ---------------- LayerNorm (fp16 output) ----------------
__global__ void ln_kernel(const float* __restrict__ x,
                          const float* __restrict__ w,
                          const float* __restrict__ b,
                          __half* __restrict__ y) {
    __shared__ float sh[8];
    long row = blockIdx.x;
    const float* xr = x + row * HID;
    __half* yr = y + row * HID;
    float vals[10];
    float sum = 0.0f;
    #pragma unroll
    for (int i = 0; i < 10; i++) { vals[i] = xr[threadIdx.x + i * 256]; sum += vals[i]; }
    float mean = block_reduce_sum(sum, sh) * (1.0f / HID);
    float sq = 0.0f;
    #pragma unroll
    for (int i = 0; i < 10; i++) { float d = vals[i] - mean; sq += d * d; }
    float var = block_reduce_sum(sq, sh) * (1.0f / HID);
    float inv = rsqrtf(var + 1e-5f);
    #pragma unroll
    for (int i = 0; i < 10; i++) {
        int idx = threadIdx.x + i * 256;
        yr[idx] = __float2half_rn((vals[i] - mean) * inv * w[idx] + b[idx]);
    }
}

// ---------------- weight transpose + fp16: WT[n][k] = half(W[k][n]) ----------------
__global__ void transpose_h_kernel(const float* __restrict__ W, __half* __restrict__ WT,
                                   int K, int N) {
    __shared__ float t[32][33];
    int k0 = blockIdx.y * 32, n0 = blockIdx.x * 32;
    int x = threadIdx.x, y = threadIdx.y;   // 32 x 8
    #pragma unroll
    for (int i = 0; i < 32; i += 8)
        t[y + i][x] = W[(long)(k0 + y + i) * N + n0 + x];
    __syncthreads();
    #pragma unroll
    for (int i = 0; i < 32; i += 8)
        WT[(long)(n0 + y + i) * K + k0 + x] = __float2half_rn(t[x][y + i]);
}

// ================= fp16 mma.sync GEMM: C[M,N] = A[M,K] @ WT[N,K]^T =================
// EPI: 1 = C=half(acc+bias) ; 2 = C=half(gelu(acc+bias)) ; 3 = C(float) += acc+bias ;
//      4 = C(float) = R + acc + bias  (fused residual)
#define GPITCH 40
#define GSTAGE (128 * GPITCH)                 // halves per operand-stage
#define G_SMEM (3 * 2 * GSTAGE * 2)           // 61440 bytes

template<int EPI>
__global__ __launch_bounds__(256, 2)
void gemm_h(const __half* __restrict__ A, int lda,
            const __half* __restrict__ B, int ldb,   // WT [N,K] row-major fp16
            void* __restrict__ Cv, int ldc,
            int K, const float* __restrict__ bias, const float* __restrict__ R) {
    extern __shared__ __half hs[];
    __half* As = hs;
    __half* Bs = hs + 3 * GSTAGE;

    int tid = threadIdx.x;
    int wid = tid >> 5, lane = tid & 31;
    int gid = lane >> 2, tig = lane & 3;
    int m_off = (wid >> 2) * 64;
    int n_off = (wid & 3) * 32;

    const __half* Ab = A + (long)blockIdx.y * 128 * lda;
    const __half* Bb = B + (long)blockIdx.x * 128 * ldb;
    uint32_t as_u = smem_u32(As), bs_u = smem_u32(Bs);

    int lr = tid >> 2;          // 0..63
    int lc = (tid & 3) * 8;     // 0,8,16,24 (halves)

    float acc[4][4][4];
    #pragma unroll
    for (int i = 0; i < 4; i++)
        #pragma unroll
        for (int j = 0; j < 4; j++)
            #pragma unroll
            for (int k = 0; k < 4; k++) acc[i][j][k] = 0.0f;

    int iters = K / 32;

    #pragma unroll
    for (int s = 0; s < 2; s++) {
        uint32_t off = (uint32_t)(s * GSTAGE + lr * GPITCH + lc) * 2u;
        cp16(as_u + off, Ab + (long)lr * lda + s * 32 + lc);
        cp16(bs_u + off, Bb + (long)lr * ldb + s * 32 + lc);
        off += 64u * GPITCH * 2u;
        cp16(as_u + off, Ab + (long)(lr + 64) * lda + s * 32 + lc);
        cp16(bs_u + off, Bb + (long)(lr + 64) * ldb + s * 32 + lc);
        CP_COMMIT();
    }

    for (int it = 0; it < iters; ++it) {
        int lt = it + 2;
        if (lt < iters) {
            int s = lt % 3;
            uint32_t off = (uint32_t)(s * GSTAGE + lr * GPITCH + lc) * 2u;
            cp16(as_u + off, Ab + (long)lr * lda + lt * 32 + lc);
            cp16(bs_u + off, Bb + (long)lr * ldb + lt * 32 + lc);
            off += 64u * GPITCH * 2u;
            cp16(as_u + off, Ab + (long)(lr + 64) * lda + lt * 32 + lc);
            cp16(bs_u + off, Bb + (long)(lr + 64) * ldb + lt * 32 + lc);
        }
        CP_COMMIT();
        CP_WAIT1();
        __syncthreads();

        const __half* as_s = As + (it % 3) * GSTAGE;
        const __half* bs_s = Bs + (it % 3) * GSTAGE;

        #pragma unroll
        for (int ks = 0; ks < 2; ks++) {
            uint32_t af[4][4];
            #pragma unroll
            for (int mt = 0; mt < 4; mt++) {
                uint32_t addr = smem_u32(as_s + (m_off + 16 * mt + (lane & 15)) * GPITCH
                                              + ks * 16 + (lane >> 4) * 8);
                ldsm_x4(af[mt], addr);
            }
            uint32_t bf[4][2];
            #pragma unroll
            for (int nt = 0; nt < 4; nt++) {
                const uint32_t* bp = (const uint32_t*)(bs_s + (n_off + 8 * nt + gid) * GPITCH
                                                            + ks * 16);
                bf[nt][0] = bp[tig];
                bf[nt][1] = bp[tig + 4];
            }
            #pragma unroll
            for (int mt = 0; mt < 4; mt++)
                #pragma unroll
                for (int nt = 0; nt < 4; nt++)
                    mma_f16(acc[mt][nt], af[mt], bf[nt][0], bf[nt][1]);
        }
        __syncthreads();
    }

    // epilogue
    #pragma unroll
    for (int mt = 0; mt < 4; mt++) {
        #pragma unroll
        for (int h2 = 0; h2 < 2; h2++) {
            long m = (long)blockIdx.y * 128 + m_off + 16 * mt + gid + h2 * 8;
            #pragma unroll
            for (int nt = 0; nt < 4; nt++) {
                int n = blockIdx.x * 128 + n_off + 8 * nt + 2 * tig;
                float2 bv = *(const float2*)(bias + n);
                float v0 = acc[mt][nt][2 * h2 + 0] + bv.x;
                float v1 = acc[mt][nt][2 * h2 + 1] + bv.y;
                if (EPI == 2) { v0 = fast_gelu(v0); v1 = fast_gelu(v1); }
                if (EPI <= 2) {
                    __half2* cp = (__half2*)((__half*)Cv + m * ldc + n);
                    *cp = __floats2half2_rn(v0, v1);
                } else if (EPI == 3) {
                    float* cp = (float*)Cv + m * ldc + n;
                    float2 c = *(float2*)cp;
                    *(float2*)cp = make_float2(c.x + v0, c.y + v1);
                } else {
                    float2 r = *(const float2*)(R + m * ldc + n);
                    float* cp = (float*)Cv + m * ldc + n;
                    *(float2*)cp = make_float2(r.x + v0, r.y + v1);
                }
            }
        }
    }
}

// ---------------- partial RoPE (in-place on fp16 q,k) ----------------
__global__ void rope_kernel(__half* __restrict__ qkv) {
    int idx = blockIdx.x * blockDim.x + threadIdx.x;
    const int total = NB * SS * NH * 16;
    if (idx >= total) return;
    int p = idx & 15;
    int h = (idx >> 4) & 31;
    int s = (idx >> 9) & (SS - 1);
    int b = idx >> 20;
    float inv = __expf(-(float)p * (9.210340371976184f / 16.0f));
    float angle = (float)s * inv;
    float sn, cs;
    sincosf(angle, &sn, &cs);
    long base = ((long)b * SS + s) * H3 + (long)h * HS;
    __half* qp = qkv + base;
    __half* kp = qkv + base + HID;
    float q1 = __half2float(qp[p]), q2 = __half2float(qp[p + 16]);
    qp[p]      = __float2half_rn(q1 * cs - q2 * sn);
    qp[p + 16] = __float2half_rn(q1 * sn + q2 * cs);
    float k1 = __half2float(kp[p]), k2 = __half2float(kp[p + 16]);
    kp[p]      = __float2half_rn(k1 * cs - k2 * sn);
    kp[p + 16] = __float2half_rn(k1 * sn + k2 * cs);
}

// ================= fp16 flash attention (P register-resident) =================
#define FBQ 128
#define FBK 64
#define KVP 88
#define FLASH_SMEM (2 * 2 * FBK * KVP * 2)    // 45056 bytes

__global__ __launch_bounds__(256, 1)
void flash_h(const __half* __restrict__ qkv, __half* __restrict__ attn) {
    extern __shared__ __half fs[];
    __half* Ks = fs;                       // [2][FBK][KVP]
    __half* Vs = fs + 2 * FBK * KVP;       // [2][FBK][KVP]

    int tid = threadIdx.x, wid = tid >> 5, lane = tid & 31;
    int gid = lane >> 2, tig = lane & 3;
    int qt = (int)gridDim.x - 1 - blockIdx.x;   // heavy tiles first
    int q0 = qt * FBQ;
    int b = blockIdx.y >> 5, h = blockIdx.y & 31;
    int m0 = wid * 16;

    const __half* qbase = qkv + (long)b * SS * H3 + (long)h * HS;
    const __half* kbase = qbase + HID;
    const __half* vbase = qbase + 2 * HID;

    int row0 = q0 + m0 + gid;
    int row1 = row0 + 8;

    // Q fragments direct from gmem (5 k16 groups over HS=80)
    uint32_t qf[5][4];
    {
        const __half* q0p = qbase + (long)row0 * H3;
        const __half* q1p = qbase + (long)row1 * H3;
        #pragma unroll
        for (int g = 0; g < 5; g++) {
            qf[g][0] = *(const uint32_t*)(q0p + 16 * g + 2 * tig);
            qf[g][1] = *(const uint32_t*)(q1p + 16 * g + 2 * tig);
            qf[g][2] = *(const uint32_t*)(q0p + 16 * g + 8 + 2 * tig);
            qf[g][3] = *(const uint32_t*)(q1p + 16 * g + 8 + 2 * tig);
        }
    }

    float oacc[10][4];
    #pragma unroll
    for (int i = 0; i < 10; i++)
        #pragma unroll
        for (int j = 0; j < 4; j++) oacc[i][j] = 0.0f;
    float mrow0 = -1e30f, mrow1 = -1e30f, lrow0 = 0.0f, lrow1 = 0.0f;

    int ntiles = q0 / FBK + 2;
    uint32_t ks_u = smem_u32(Ks), vs_u = smem_u32(Vs);

    // prologue: tile 0 -> stage 0  (640 16B-chunks per operand)
    #pragma unroll
    for (int i = 0; i < 3; i++) {
        int c = tid + i * 256;
        if (c < 640) {
            int r = c / 10, cc = c % 10;
            uint32_t off = (uint32_t)(r * KVP + cc * 8) * 2u;
            cp16(ks_u + off, kbase + (long)r * H3 + cc * 8);
            cp16(vs_u + off, vbase + (long)r * H3 + cc * 8);
        }
    }
    CP_COMMIT();

    const float scale = 0.11180339887498949f;

    for (int t = 0; t < ntiles; ++t) {
        int stage = t & 1;
        __syncthreads();
        if (t + 1 < ntiles) {
            int kv1 = (t + 1) * FBK;
            int st1 = (t + 1) & 1;
            #pragma unroll
            for (int i = 0; i < 3; i++) {
                int c = tid + i * 256;
                if (c < 640) {
                    int r = c / 10, cc = c % 10;
                    uint32_t off = (uint32_t)((st1 * FBK + r) * KVP + cc * 8) * 2u;
                    cp16(ks_u + off, kbase + (long)(kv1 + r) * H3 + cc * 8);
                    cp16(vs_u + off, vbase + (long)(kv1 + r) * H3 + cc * 8);
                }
            }
        }
        CP_COMMIT();
        CP_WAIT1();
        __syncthreads();

        // ---- S = Q @ K^T (warp: 16 x 64) ----
        float sacc[8][4];
        #pragma unroll
        for (int i = 0; i < 8; i++)
            #pragma unroll
            for (int j = 0; j < 4; j++) sacc[i][j] = 0.0f;

        const __half* kt = Ks + stage * FBK * KVP;
        #pragma unroll
        for (int nt = 0; nt < 8; nt++) {
            const uint32_t* bp = (const uint32_t*)(kt + (8 * nt + gid) * KVP);
            #pragma unroll
            for (int g = 0; g < 5; g++)
                mma_f16(sacc[nt], qf[g], bp[8 * g + tig], bp[8 * g + 4 + tig]);
        }

        // ---- scale + causal mask ----
        int kv0 = t * FBK;
        bool need_mask = (t >= ntiles - 2);
        #pragma unroll
        for (int nt = 0; nt < 8; nt++) {
            int c0 = kv0 + nt * 8 + 2 * tig;
            #pragma unroll
            for (int j = 0; j < 4; j++) sacc[nt][j] *= scale;
            if (need_mask) {
                if (c0 > row0)     sacc[nt][0] = -1e30f;
                if (c0 + 1 > row0) sacc[nt][1] = -1e30f;
                if (c0 > row1)     sacc[nt][2] = -1e30f;
                if (c0 + 1 > row1) sacc[nt][3] = -1e30f;
            }
        }

        // ---- online softmax ----
        float rm0 = -1e30f, rm1 = -1e30f;
        #pragma unroll
        for (int nt = 0; nt < 8; nt++) {
            rm0 = fmaxf(rm0, fmaxf(sacc[nt][0], sacc[nt][1]));
            rm1 = fmaxf(rm1, fmaxf(sacc[nt][2], sacc[nt][3]));
        }
        rm0 = fmaxf(rm0, __shfl_xor_sync(0xffffffffu, rm0, 1));
        rm0 = fmaxf(rm0, __shfl_xor_sync(0xffffffffu, rm0, 2));
        rm1 = fmaxf(rm1, __shfl_xor_sync(0xffffffffu, rm1, 1));
        rm1 = fmaxf(rm1, __shfl_xor_sync(0xffffffffu, rm1, 2));
        float mn0 = fmaxf(mrow0, rm0);
        float mn1 = fmaxf(mrow1, rm1);

        float rs0 = 0.0f, rs1 = 0.0f;
        uint32_t ph[8][2];
        #pragma unroll
        for (int nt = 0; nt < 8; nt++) {
            float p0 = __expf(sacc[nt][0] - mn0);
            float p1 = __expf(sacc[nt][1] - mn0);
            float p2 = __expf(sacc[nt][2] - mn1);
            float p3 = __expf(sacc[nt][3] - mn1);
            rs0 += p0 + p1;
            rs1 += p2 + p3;
            ph[nt][0] = packh2(p0, p1);
            ph[nt][1] = packh2(p2, p3);
        }
        rs0 += __shfl_xor_sync(0xffffffffu, rs0, 1);
        rs0 += __shfl_xor_sync(0xffffffffu, rs0, 2);
        rs1 += __shfl_xor_sync(0xffffffffu, rs1, 1);
        rs1 += __shfl_xor_sync(0xffffffffu, rs1, 2);

        float a0 = __expf(mrow0 - mn0);
        float a1 = __expf(mrow1 - mn1);
        lrow0 = lrow0 * a0 + rs0;
        lrow1 = lrow1 * a1 + rs1;
        mrow0 = mn0; mrow1 = mn1;
        #pragma unroll
        for (int nt = 0; nt < 10; nt++) {
            oacc[nt][0] *= a0; oacc[nt][1] *= a0;
            oacc[nt][2] *= a1; oacc[nt][3] *= a1;
        }

        // ---- O += P @ V  (P in registers; V via ldmatrix.trans) ----
        const __half* vt = Vs + stage * FBK * KVP;
        #pragma unroll
        for (int g = 0; g < 4; g++) {
            uint32_t af[4] = { ph[2 * g][0], ph[2 * g][1], ph[2 * g + 1][0], ph[2 * g + 1][1] };
            #pragma unroll
            for (int nt = 0; nt < 10; nt++) {
                uint32_t b0, b1;
                uint32_t addr = smem_u32(vt + (16 * g + (lane & 15)) * KVP + nt * 8);
                ldsm_x2_trans(b0, b1, addr);
                mma_f16(oacc[nt], af, b0, b1);
            }
        }
    }

    // ---- epilogue ----
    float inv0 = 1.0f / lrow0;
    float inv1 = 1.0f / lrow1;
    __half* o0 = attn + ((long)b * SS + row0) * HID + h * HS;
    __half* o1 = attn + ((long)b * SS + row1) * HID + h * HS;
    #pragma unroll
    for (int nt = 0; nt < 10; nt++) {
        int cc = nt * 8 + 2 * tig;
        *(__half2*)(o0 + cc) = __floats2half2_rn(oacc[nt][0] * inv0, oacc[nt][1] * inv0);
        *(__half2*)(o1 + cc) = __floats2half2_rn(oacc[nt][2] * inv1, oacc[nt][3] * inv1);
    }
}

// ---------------- host-side launcher ----------------
static void* sym_addr(const void* symbol) {
    void* p = nullptr;
    cudaGetSymbolAddress(&p, symbol);
    return p;
}

extern "C" void kernel_launch(void* const* d_in, const int* in_sizes, int n_in,
                              void* d_out, int out_size) {
    const float* hidden = (const float*)d_in[0];
    const float* ln_w   = (const float*)d_in[1];
    const float* ln_b   = (const float*)d_in[2];
    const float* qkv_w  = (const float*)d_in[3];
    const float* qkv_b  = (const float*)d_in[4];
    const float* out_w  = (const float*)d_in[5];
    const float* out_b  = (const float*)d_in[6];
    const float* fc1_w  = (const float*)d_in[7];
    const float* fc1_b  = (const float*)d_in[8];
    const float* fc2_w  = (const float*)d_in[9];
    const float* fc2_b  = (const float*)d_in[10];
    float* out = (float*)d_out;

    __half* ln    = (__half*)sym_addr(g_ln);
    __half* qkv   = (__half*)sym_addr(g_qkv);
    __half* attn  = (__half*)sym_addr(g_attn);
    __half* fc1   = (__half*)sym_addr(g_fc1);
    __half* wqkvT = (__half*)sym_addr(g_wqkv_t);
    __half* woutT = (__half*)sym_addr(g_wout_t);
    __half* w1T   = (__half*)sym_addr(g_w1_t);
    __half* w2T   = (__half*)sym_addr(g_w2_t);

    cudaFuncSetAttribute(gemm_h<1>, cudaFuncAttributeMaxDynamicSharedMemorySize, G_SMEM);
    cudaFuncSetAttribute(gemm_h<2>, cudaFuncAttributeMaxDynamicSharedMemorySize, G_SMEM);
    cudaFuncSetAttribute(gemm_h<3>, cudaFuncAttributeMaxDynamicSharedMemorySize, G_SMEM);
    cudaFuncSetAttribute(gemm_h<4>, cudaFuncAttributeMaxDynamicSharedMemorySize, G_SMEM);
    cudaFuncSetAttribute(flash_h, cudaFuncAttributeMaxDynamicSharedMemorySize, FLASH_SMEM);

    // 0. transpose weights to fp16 [N,K]
    {
        dim3 blk(32, 8);
        transpose_h_kernel<<<dim3(H3 / 32, HID / 32), blk>>>(qkv_w, wqkvT, HID, H3);
        transpose_h_kernel<<<dim3(HID / 32, HID / 32), blk>>>(out_w, woutT, HID, HID);
        transpose_h_kernel<<<dim3(H4 / 32, HID / 32), blk>>>(fc1_w, w1T, HID, H4);
        transpose_h_kernel<<<dim3(HID / 32, H4 / 32), blk>>>(fc2_w, w2T, H4, HID);
    }

    // 1. LayerNorm -> fp16
    ln_kernel<<<ROWS, 256>>>(hidden, ln_w, ln_b, ln);

    // 2. QKV = half(ln @ Wqkv + b)
    gemm_h<1><<<dim3(H3 / 128, ROWS / 128), 256, G_SMEM>>>(
        ln, HID, wqkvT, HID, qkv, H3, HID, qkv_b, nullptr);

    // 3. RoPE (in place)
    {
        int total = NB * SS * NH * 16;
        rope_kernel<<<(total + 255) / 256, 256>>>(qkv);
    }

    // 4. flash attention -> attn (fp16)
    flash_h<<<dim3(SS / FBQ, NB * NH), 256, FLASH_SMEM>>>(qkv, attn);

    // 5. fc1 = half(gelu(ln @ W1 + b1))
    gemm_h<2><<<dim3(H4 / 128, ROWS / 128), 256, G_SMEM>>>(
        ln, HID, w1T, HID, fc1, H4, HID, fc1_b, nullptr);

    // 6. out = hidden + attn @ Wo + bo   (fused residual)
    gemm_h<4><<<dim3(HID / 128, ROWS / 128), 256, G_SMEM>>>(
        attn, HID, woutT, HID, out, HID, HID, out_b, hidden);

    // 7. out += fc1 @ W2 + b2
    gemm_h<3><<<dim3(HID / 128, ROWS / 128), 256, G_SMEM>>>(
        fc1, H4, w2T, H4, out, HID, H4, fc2_b, nullptr);
}

// round 9
// speedup vs baseline: 7.6071x; 1.0182x over previous
#include <cuda_runtime.h>
#include <cuda_fp16.h>
#include <math.h>
#include <stdint.h>

#define NB 2
#define SS 2048
#define NH 32
#define HS 80
#define HID 2560
#define H3 7680
#define H4 10240
#define ROWS (NB*SS)          // 4096

// ---------------- scratch (static device globals; no allocation) ----------------
__device__ __half g_ln[(long)ROWS * HID];
__device__ __half g_qkv[(long)ROWS * H3];
__device__ __half g_attn[(long)ROWS * HID];
__device__ __half g_fc1[(long)ROWS * H4];
// transposed fp16 weights: WT[n][k] = half(W[k][n])
__device__ __half g_wqkv_t[(long)H3 * HID];
__device__ __half g_wout_t[(long)HID * HID];
__device__ __half g_w1_t[(long)H4 * HID];
__device__ __half g_w2_t[(long)HID * H4];

// ---------------- small helpers ----------------
__device__ __forceinline__ float fast_gelu(float x) {
    const float c = 0.7978845608028654f;
    float x3 = x * x * x;
    return 0.5f * x * (1.0f + tanhf(c * (x + 0.044715f * x3)));
}

__device__ __forceinline__ uint32_t smem_u32(const void* p) {
    uint32_t a;
    asm("{ .reg .u64 t; cvta.to.shared.u64 t, %1; cvt.u32.u64 %0, t; }" : "=r"(a) : "l"(p));
    return a;
}

__device__ __forceinline__ void cp16(uint32_t dst, const void* src) {
    asm volatile("cp.async.cg.shared.global [%0], [%1], 16;" :: "r"(dst), "l"(src));
}
#define CP_COMMIT() asm volatile("cp.async.commit_group;" ::: "memory")
#define CP_WAIT1()  asm volatile("cp.async.wait_group 1;" ::: "memory")
#define CP_WAIT2()  asm volatile("cp.async.wait_group 2;" ::: "memory")

__device__ __forceinline__ void mma_f16(float* d, const uint32_t* a, uint32_t b0, uint32_t b1) {
    asm volatile("mma.sync.aligned.m16n8k16.row.col.f32.f16.f16.f32 "
        "{%0,%1,%2,%3}, {%4,%5,%6,%7}, {%8,%9}, {%0,%1,%2,%3};"
        : "+f"(d[0]), "+f"(d[1]), "+f"(d[2]), "+f"(d[3])
        : "r"(a[0]), "r"(a[1]), "r"(a[2]), "r"(a[3]), "r"(b0), "r"(b1));
}

__device__ __forceinline__ void ldsm_x4(uint32_t* r, uint32_t addr) {
    asm volatile("ldmatrix.sync.aligned.m8n8.x4.shared.b16 {%0,%1,%2,%3}, [%4];"
        : "=r"(r[0]), "=r"(r[1]), "=r"(r[2]), "=r"(r[3]) : "r"(addr));
}
__device__ __forceinline__ void ldsm_x2_trans(uint32_t& r0, uint32_t& r1, uint32_t addr) {
    asm volatile("ldmatrix.sync.aligned.m8n8.x2.trans.shared.b16 {%0,%1}, [%2];"
        : "=r"(r0), "=r"(r1) : "r"(addr));
}

__device__ __forceinline__ uint32_t packh2(float a, float b) {
    __half2 h = __floats2half2_rn(a, b);
    return *reinterpret_cast<uint32_t*>(&h);
}

// ---------------- block reduce ----------------
__device__ __forceinline__ float block_reduce_sum(float v, float* sh) {
    #pragma unroll
    for (int o = 16; o > 0; o >>= 1) v += __shfl_xor_sync(0xffffffffu, v, o);
    int wid = threadIdx.x >> 5;
    if ((threadIdx.x & 31) == 0) sh[wid] = v;
    __syncthreads();
    if (threadIdx.x < 32) {
        float t = (threadIdx.x < 8) ? sh[threadIdx.x] : 0.0f;
        #pragma unroll
        for (int o = 4; o > 0; o >>= 1) t += __shfl_xor_sync(0xffffffffu, t, o);
        if (threadIdx.x == 0) sh[0] = t;
    }
    __syncthreads();
    float r = sh[0];
    __syncthreads();
    return r;
}

// ---------------- LayerNorm (fp16 output) ----------------
__global__ void ln_kernel(const float* __restrict__ x,
                          const float* __restrict__ w,
                          const float* __restrict__ b,
                          __half* __restrict__ y) {
    __shared__ float sh[8];
    long row = blockIdx.x;
    const float* xr = x + row * HID;
    __half* yr = y + row * HID;
    float vals[10];
    float sum = 0.0f;
    #pragma unroll
    for (int i = 0; i < 10; i++) { vals[i] = xr[threadIdx.x + i * 256]; sum += vals[i]; }
    float mean = block_reduce_sum(sum, sh) * (1.0f / HID);
    float sq = 0.0f;
    #pragma unroll
    for (int i = 0; i < 10; i++) { float d = vals[i] - mean; sq += d * d; }
    float var = block_reduce_sum(sq, sh) * (1.0f / HID);
    float inv = rsqrtf(var + 1e-5f);
    #pragma unroll
    for (int i = 0; i < 10; i++) {
        int idx = threadIdx.x + i * 256;
        yr[idx] = __float2half_rn((vals[i] - mean) * inv * w[idx] + b[idx]);
    }
}

// ---------------- weight transpose + fp16: WT[n][k] = half(W[k][n]) ----------------
__global__ void transpose_h_kernel(const float* __restrict__ W, __half* __restrict__ WT,
                                   int K, int N) {
    __shared__ float t[32][33];
    int k0 = blockIdx.y * 32, n0 = blockIdx.x * 32;
    int x = threadIdx.x, y = threadIdx.y;   // 32 x 8
    #pragma unroll
    for (int i = 0; i < 32; i += 8)
        t[y + i][x] = W[(long)(k0 + y + i) * N + n0 + x];
    __syncthreads();
    #pragma unroll
    for (int i = 0; i < 32; i += 8)
        WT[(long)(n0 + y + i) * K + k0 + x] = __float2half_rn(t[x][y + i]);
}

// ================= fp16 mma GEMM infrastructure =================
#define GSTAGES 4
#define GPITCH 40
#define GSTAGE (128 * GPITCH)                     // halves per operand-stage
#define G_SMEM (GSTAGES * 2 * GSTAGE * 2)         // 81920 bytes

// compute one BK=32 step from smem stage into acc[4][4][4]
__device__ __forceinline__ void gemm_compute_stage(
    const __half* as_s, const __half* bs_s,
    int m_off, int n_off, int lane, int gid, int tig,
    float acc[4][4][4]) {
    #pragma unroll
    for (int ks = 0; ks < 2; ks++) {
        uint32_t af[4][4];
        #pragma unroll
        for (int mt = 0; mt < 4; mt++) {
            uint32_t addr = smem_u32(as_s + (m_off + 16 * mt + (lane & 15)) * GPITCH
                                          + ks * 16 + (lane >> 4) * 8);
            ldsm_x4(af[mt], addr);
        }
        uint32_t bf[4][2];
        #pragma unroll
        for (int nt = 0; nt < 4; nt++) {
            const uint32_t* bp = (const uint32_t*)(bs_s + (n_off + 8 * nt + gid) * GPITCH
                                                        + ks * 16);
            bf[nt][0] = bp[tig];
            bf[nt][1] = bp[tig + 4];
        }
        #pragma unroll
        for (int mt = 0; mt < 4; mt++)
            #pragma unroll
            for (int nt = 0; nt < 4; nt++)
                mma_f16(acc[mt][nt], af[mt], bf[nt][0], bf[nt][1]);
    }
}

// ---------------- merged QKV + FC1 GEMM (both read ln, K=HID) ----------------
// grid: (H3/128 + H4/128 = 140, ROWS/128 = 32)
__global__ __launch_bounds__(256, 2)
void gemm_qkv_fc1(const __half* __restrict__ ln,
                  const __half* __restrict__ wqkvT, const __half* __restrict__ w1T,
                  __half* __restrict__ qkv, __half* __restrict__ fc1,
                  const float* __restrict__ qkv_b, const float* __restrict__ fc1_b) {
    extern __shared__ __half hs[];
    __half* As = hs;
    __half* Bs = hs + GSTAGES * GSTAGE;

    int tid = threadIdx.x;
    int wid = tid >> 5, lane = tid & 31;
    int gid = lane >> 2, tig = lane & 3;
    int m_off = (wid >> 2) * 64;
    int n_off = (wid & 3) * 32;

    int bx = blockIdx.x;
    bool is_fc1 = bx >= (H3 / 128);
    int nb = is_fc1 ? bx - H3 / 128 : bx;
    const __half* Bb = is_fc1 ? (w1T + (long)nb * 128 * HID)
                              : (wqkvT + (long)nb * 128 * HID);
    const __half* Ab = ln + (long)blockIdx.y * 128 * HID;
    uint32_t as_u = smem_u32(As), bs_u = smem_u32(Bs);

    int lr = tid >> 2;          // 0..63
    int lc = (tid & 3) * 8;     // 0,8,16,24 halves

    float acc[4][4][4];
    #pragma unroll
    for (int i = 0; i < 4; i++)
        #pragma unroll
        for (int j = 0; j < 4; j++)
            #pragma unroll
            for (int k = 0; k < 4; k++) acc[i][j][k] = 0.0f;

    const int iters = HID / 32;   // 80

    #pragma unroll
    for (int s = 0; s < 3; s++) {
        uint32_t off = (uint32_t)(s * GSTAGE + lr * GPITCH + lc) * 2u;
        cp16(as_u + off, Ab + (long)lr * HID + s * 32 + lc);
        cp16(bs_u + off, Bb + (long)lr * HID + s * 32 + lc);
        off += 64u * GPITCH * 2u;
        cp16(as_u + off, Ab + (long)(lr + 64) * HID + s * 32 + lc);
        cp16(bs_u + off, Bb + (long)(lr + 64) * HID + s * 32 + lc);
        CP_COMMIT();
    }

    for (int it = 0; it < iters; ++it) {
        CP_WAIT2();
        __syncthreads();
        int lt = it + 3;
        if (lt < iters) {
            int s = lt & 3;
            uint32_t off = (uint32_t)(s * GSTAGE + lr * GPITCH + lc) * 2u;
            cp16(as_u + off, Ab + (long)lr * HID + lt * 32 + lc);
            cp16(bs_u + off, Bb + (long)lr * HID + lt * 32 + lc);
            off += 64u * GPITCH * 2u;
            cp16(as_u + off, Ab + (long)(lr + 64) * HID + lt * 32 + lc);
            cp16(bs_u + off, Bb + (long)(lr + 64) * HID + lt * 32 + lc);
        }
        CP_COMMIT();
        gemm_compute_stage(As + (it & 3) * GSTAGE, Bs + (it & 3) * GSTAGE,
                           m_off, n_off, lane, gid, tig, acc);
    }

    // epilogue
    const float* bias = is_fc1 ? fc1_b : qkv_b;
    int ldc = is_fc1 ? H4 : H3;
    __half* C = is_fc1 ? fc1 : qkv;
    #pragma unroll
    for (int mt = 0; mt < 4; mt++) {
        #pragma unroll
        for (int h2 = 0; h2 < 2; h2++) {
            long m = (long)blockIdx.y * 128 + m_off + 16 * mt + gid + h2 * 8;
            #pragma unroll
            for (int nt = 0; nt < 4; nt++) {
                int n = nb * 128 + n_off + 8 * nt + 2 * tig;
                float2 bv = *(const float2*)(bias + n);
                float v0 = acc[mt][nt][2 * h2 + 0] + bv.x;
                float v1 = acc[mt][nt][2 * h2 + 1] + bv.y;
                if (is_fc1) { v0 = fast_gelu(v0); v1 = fast_gelu(v1); }
                *(__half2*)(C + m * ldc + n) = __floats2half2_rn(v0, v1);
            }
        }
    }
}

// ---------------- dual-phase GEMM: out = hidden + attn@Wo + b_o + fc1@W2 + b_2 ----------------
// grid: (HID/128 = 20, ROWS/128 = 32); K phases: 80 iters (attn,Wo) + 320 iters (fc1,W2)
__global__ __launch_bounds__(256, 2)
void gemm_dual(const __half* __restrict__ attn, const __half* __restrict__ woutT,
               const __half* __restrict__ fc1, const __half* __restrict__ w2T,
               const float* __restrict__ hidden, float* __restrict__ out,
               const float* __restrict__ out_b, const float* __restrict__ fc2_b) {
    extern __shared__ __half hs[];
    __half* As = hs;
    __half* Bs = hs + GSTAGES * GSTAGE;

    int tid = threadIdx.x;
    int wid = tid >> 5, lane = tid & 31;
    int gid = lane >> 2, tig = lane & 3;
    int m_off = (wid >> 2) * 64;
    int n_off = (wid & 3) * 32;

    const __half* A1 = attn + (long)blockIdx.y * 128 * HID;
    const __half* B1 = woutT + (long)blockIdx.x * 128 * HID;
    const __half* A2 = fc1 + (long)blockIdx.y * 128 * H4;
    const __half* B2 = w2T + (long)blockIdx.x * 128 * H4;
    uint32_t as_u = smem_u32(As), bs_u = smem_u32(Bs);

    int lr = tid >> 2;
    int lc = (tid & 3) * 8;

    const int it1 = HID / 32;            // 80
    const int iters = it1 + H4 / 32;     // 400

    float acc[4][4][4];
    #pragma unroll
    for (int i = 0; i < 4; i++)
        #pragma unroll
        for (int j = 0; j < 4; j++)
            #pragma unroll
            for (int k = 0; k < 4; k++) acc[i][j][k] = 0.0f;

    // load issuer for global iter gi into stage s
    auto issue = [&](int gi, int s) {
        const __half* ap; const __half* bp; long lda_; int k0;
        if (gi < it1) { ap = A1; bp = B1; lda_ = HID; k0 = gi * 32; }
        else          { ap = A2; bp = B2; lda_ = H4;  k0 = (gi - it1) * 32; }
        uint32_t off = (uint32_t)(s * GSTAGE + lr * GPITCH + lc) * 2u;
        cp16(as_u + off, ap + (long)lr * lda_ + k0 + lc);
        cp16(bs_u + off, bp + (long)lr * lda_ + k0 + lc);
        off += 64u * GPITCH * 2u;
        cp16(as_u + off, ap + (long)(lr + 64) * lda_ + k0 + lc);
        cp16(bs_u + off, bp + (long)(lr + 64) * lda_ + k0 + lc);
    };

    #pragma unroll
    for (int s = 0; s < 3; s++) { issue(s, s); CP_COMMIT(); }

    for (int it = 0; it < iters; ++it) {
        CP_WAIT2();
        __syncthreads();
        int lt = it + 3;
        if (lt < iters) issue(lt, lt & 3);
        CP_COMMIT();
        gemm_compute_stage(As + (it & 3) * GSTAGE, Bs + (it & 3) * GSTAGE,
                           m_off, n_off, lane, gid, tig, acc);
    }

    #pragma unroll
    for (int mt = 0; mt < 4; mt++) {
        #pragma unroll
        for (int h2 = 0; h2 < 2; h2++) {
            long m = (long)blockIdx.y * 128 + m_off + 16 * mt + gid + h2 * 8;
            #pragma unroll
            for (int nt = 0; nt < 4; nt++) {
                int n = blockIdx.x * 128 + n_off + 8 * nt + 2 * tig;
                float2 b1 = *(const float2*)(out_b + n);
                float2 b2 = *(const float2*)(fc2_b + n);
                float2 r = *(const float2*)(hidden + m * HID + n);
                float v0 = acc[mt][nt][2 * h2 + 0] + b1.x + b2.x + r.x;
                float v1 = acc[mt][nt][2 * h2 + 1] + b1.y + b2.y + r.y;
                *(float2*)(out + m * HID + n) = make_float2(v0, v1);
            }
        }
    }
}

// ---------------- partial RoPE (in-place on fp16 q,k) ----------------
__global__ void rope_kernel(__half* __restrict__ qkv) {
    int idx = blockIdx.x * blockDim.x + threadIdx.x;
    const int total = NB * SS * NH * 16;
    if (idx >= total) return;
    int p = idx & 15;
    int h = (idx >> 4) & 31;
    int s = (idx >> 9) & (SS - 1);
    int b = idx >> 20;
    float inv = __expf(-(float)p * (9.210340371976184f / 16.0f));
    float angle = (float)s * inv;
    float sn, cs;
    sincosf(angle, &sn, &cs);
    long base = ((long)b * SS + s) * H3 + (long)h * HS;
    __half* qp = qkv + base;
    __half* kp = qkv + base + HID;
    float q1 = __half2float(qp[p]), q2 = __half2float(qp[p + 16]);
    qp[p]      = __float2half_rn(q1 * cs - q2 * sn);
    qp[p + 16] = __float2half_rn(q1 * sn + q2 * cs);
    float k1 = __half2float(kp[p]), k2 = __half2float(kp[p + 16]);
    kp[p]      = __float2half_rn(k1 * cs - k2 * sn);
    kp[p + 16] = __float2half_rn(k1 * sn + k2 * cs);
}

// ================= fp16 flash attention (3-stage, single sync/iter) =================
#define FBQ 128
#define FBK 64
#define KVP 88
#define FSTAGE (FBK * KVP)                       // halves per operand-stage
#define FLASH_SMEM (3 * 2 * FSTAGE * 2)          // 67584 bytes

__global__ __launch_bounds__(256, 1)
void flash_h(const __half* __restrict__ qkv, __half* __restrict__ attn) {
    extern __shared__ __half fs[];
    __half* Ks = fs;                       // [3][FBK][KVP]
    __half* Vs = fs + 3 * FSTAGE;          // [3][FBK][KVP]

    int tid = threadIdx.x, wid = tid >> 5, lane = tid & 31;
    int gid = lane >> 2, tig = lane & 3;
    int qt = (int)gridDim.x - 1 - blockIdx.x;   // heavy tiles first
    int q0 = qt * FBQ;
    int b = blockIdx.y >> 5, h = blockIdx.y & 31;
    int m0 = wid * 16;

    const __half* qbase = qkv + (long)b * SS * H3 + (long)h * HS;
    const __half* kbase = qbase + HID;
    const __half* vbase = qbase + 2 * HID;

    int row0 = q0 + m0 + gid;
    int row1 = row0 + 8;

    // Q fragments direct from gmem (5 k16 groups over HS=80)
    uint32_t qf[5][4];
    {
        const __half* q0p = qbase + (long)row0 * H3;
        const __half* q1p = qbase + (long)row1 * H3;
        #pragma unroll
        for (int g = 0; g < 5; g++) {
            qf[g][0] = *(const uint32_t*)(q0p + 16 * g + 2 * tig);
            qf[g][1] = *(const uint32_t*)(q1p + 16 * g + 2 * tig);
            qf[g][2] = *(const uint32_t*)(q0p + 16 * g + 8 + 2 * tig);
            qf[g][3] = *(const uint32_t*)(q1p + 16 * g + 8 + 2 * tig);
        }
    }

    float oacc[10][4];
    #pragma unroll
    for (int i = 0; i < 10; i++)
        #pragma unroll
        for (int j = 0; j < 4; j++) oacc[i][j] = 0.0f;
    float mrow0 = -1e30f, mrow1 = -1e30f, lrow0 = 0.0f, lrow1 = 0.0f;

    int ntiles = q0 / FBK + 2;
    uint32_t ks_u = smem_u32(Ks), vs_u = smem_u32(Vs);

    auto issue_tile = [&](int t, int stage) {
        int kv = t * FBK;
        #pragma unroll
        for (int i = 0; i < 3; i++) {
            int c = tid + i * 256;
            if (c < 640) {
                int r = c / 10, cc = c % 10;
                uint32_t off = (uint32_t)((stage * FBK + r) * KVP + cc * 8) * 2u;
                cp16(ks_u + off, kbase + (long)(kv + r) * H3 + cc * 8);
                cp16(vs_u + off, vbase + (long)(kv + r) * H3 + cc * 8);
            }
        }
    };

    issue_tile(0, 0); CP_COMMIT();
    issue_tile(1, 1); CP_COMMIT();

    const float scale = 0.11180339887498949f;

    for (int t = 0; t < ntiles; ++t) {
        CP_WAIT1();
        __syncthreads();
        if (t + 2 < ntiles) issue_tile(t + 2, (t + 2) % 3);
        CP_COMMIT();
        int stage = t % 3;

        // ---- S = Q @ K^T (warp: 16 x 64) ----
        float sacc[8][4];
        #pragma unroll
        for (int i = 0; i < 8; i++)
            #pragma unroll
            for (int j = 0; j < 4; j++) sacc[i][j] = 0.0f;

        const __half* kt = Ks + stage * FSTAGE;
        #pragma unroll
        for (int nt = 0; nt < 8; nt++) {
            const uint32_t* bp = (const uint32_t*)(kt + (8 * nt + gid) * KVP);
            #pragma unroll
            for (int g = 0; g < 5; g++)
                mma_f16(sacc[nt], qf[g], bp[8 * g + tig], bp[8 * g + 4 + tig]);
        }

        // ---- scale + causal mask ----
        int kv0 = t * FBK;
        bool need_mask = (t >= ntiles - 2);
        #pragma unroll
        for (int nt = 0; nt < 8; nt++) {
            int c0 = kv0 + nt * 8 + 2 * tig;
            #pragma unroll
            for (int j = 0; j < 4; j++) sacc[nt][j] *= scale;
            if (need_mask) {
                if (c0 > row0)     sacc[nt][0] = -1e30f;
                if (c0 + 1 > row0) sacc[nt][1] = -1e30f;
                if (c0 > row1)     sacc[nt][2] = -1e30f;
                if (c0 + 1 > row1) sacc[nt][3] = -1e30f;
            }
        }

        // ---- online softmax ----
        float rm0 = -1e30f, rm1 = -1e30f;
        #pragma unroll
        for (int nt = 0; nt < 8; nt++) {
            rm0 = fmaxf(rm0, fmaxf(sacc[nt][0], sacc[nt][1]));
            rm1 = fmaxf(rm1, fmaxf(sacc[nt][2], sacc[nt][3]));
        }
        rm0 = fmaxf(rm0, __shfl_xor_sync(0xffffffffu, rm0, 1));
        rm0 = fmaxf(rm0, __shfl_xor_sync(0xffffffffu, rm0, 2));
        rm1 = fmaxf(rm1, __shfl_xor_sync(0xffffffffu, rm1, 1));
        rm1 = fmaxf(rm1, __shfl_xor_sync(0xffffffffu, rm1, 2));
        float mn0 = fmaxf(mrow0, rm0);
        float mn1 = fmaxf(mrow1, rm1);

        float rs0 = 0.0f, rs1 = 0.0f;
        uint32_t ph[8][2];
        #pragma unroll
        for (int nt = 0; nt < 8; nt++) {
            float p0 = __expf(sacc[nt][0] - mn0);
            float p1 = __expf(sacc[nt][1] - mn0);
            float p2 = __expf(sacc[nt][2] - mn1);
            float p3 = __expf(sacc[nt][3] - mn1);
            rs0 += p0 + p1;
            rs1 += p2 + p3;
            ph[nt][0] = packh2(p0, p1);
            ph[nt][1] = packh2(p2, p3);
        }
        rs0 += __shfl_xor_sync(0xffffffffu, rs0, 1);
        rs0 += __shfl_xor_sync(0xffffffffu, rs0, 2);
        rs1 += __shfl_xor_sync(0xffffffffu, rs1, 1);
        rs1 += __shfl_xor_sync(0xffffffffu, rs1, 2);

        float a0 = __expf(mrow0 - mn0);
        float a1 = __expf(mrow1 - mn1);
        lrow0 = lrow0 * a0 + rs0;
        lrow1 = lrow1 * a1 + rs1;
        mrow0 = mn0; mrow1 = mn1;
        #pragma unroll
        for (int nt = 0; nt < 10; nt++) {
            oacc[nt][0] *= a0; oacc[nt][1] *= a0;
            oacc[nt][2] *= a1; oacc[nt][3] *= a1;
        }

        // ---- O += P @ V  (P in registers; V via ldmatrix.trans) ----
        const __half* vt = Vs + stage * FSTAGE;
        #pragma unroll
        for (int g = 0; g < 4; g++) {
            uint32_t af[4] = { ph[2 * g][0], ph[2 * g][1], ph[2 * g + 1][0], ph[2 * g + 1][1] };
            #pragma unroll
            for (int nt = 0; nt < 10; nt++) {
                uint32_t b0, b1;
                uint32_t addr = smem_u32(vt + (16 * g + (lane & 15)) * KVP + nt * 8);
                ldsm_x2_trans(b0, b1, addr);
                mma_f16(oacc[nt], af, b0, b1);
            }
        }
    }

    // ---- epilogue ----
    float inv0 = 1.0f / lrow0;
    float inv1 = 1.0f / lrow1;
    __half* o0 = attn + ((long)b * SS + row0) * HID + h * HS;
    __half* o1 = attn + ((long)b * SS + row1) * HID + h * HS;
    #pragma unroll
    for (int nt = 0; nt < 10; nt++) {
        int cc = nt * 8 + 2 * tig;
        *(__half2*)(o0 + cc) = __floats2half2_rn(oacc[nt][0] * inv0, oacc[nt][1] * inv0);
        *(__half2*)(o1 + cc) = __floats2half2_rn(oacc[nt][2] * inv1, oacc[nt][3] * inv1);
    }
}

// ---------------- host-side launcher ----------------
static void* sym_addr(const void* symbol) {
    void* p = nullptr;
    cudaGetSymbolAddress(&p, symbol);
    return p;
}

extern "C" void kernel_launch(void* const* d_in, const int* in_sizes, int n_in,
                              void* d_out, int out_size) {
    const float* hidden = (const float*)d_in[0];
    const float* ln_w   = (const float*)d_in[1];
    const float* ln_b   = (const float*)d_in[2];
    const float* qkv_w  = (const float*)d_in[3];
    const float* qkv_b  = (const float*)d_in[4];
    const float* out_w  = (const float*)d_in[5];
    const float* out_b  = (const float*)d_in[6];
    const float* fc1_w  = (const float*)d_in[7];
    const float* fc1_b  = (const float*)d_in[8];
    const float* fc2_w  = (const float*)d_in[9];
    const float* fc2_b  = (const float*)d_in[10];
    float* out = (float*)d_out;

    __half* ln    = (__half*)sym_addr(g_ln);
    __half* qkv   = (__half*)sym_addr(g_qkv);
    __half* attn  = (__half*)sym_addr(g_attn);
    __half* fc1   = (__half*)sym_addr(g_fc1);
    __half* wqkvT = (__half*)sym_addr(g_wqkv_t);
    __half* woutT = (__half*)sym_addr(g_wout_t);
    __half* w1T   = (__half*)sym_addr(g_w1_t);
    __half* w2T   = (__half*)sym_addr(g_w2_t);

    cudaFuncSetAttribute(gemm_qkv_fc1, cudaFuncAttributeMaxDynamicSharedMemorySize, G_SMEM);
    cudaFuncSetAttribute(gemm_dual, cudaFuncAttributeMaxDynamicSharedMemorySize, G_SMEM);
    cudaFuncSetAttribute(flash_h, cudaFuncAttributeMaxDynamicSharedMemorySize, FLASH_SMEM);

    // 0. transpose weights to fp16 [N,K]
    {
        dim3 blk(32, 8);
        transpose_h_kernel<<<dim3(H3 / 32, HID / 32), blk>>>(qkv_w, wqkvT, HID, H3);
        transpose_h_kernel<<<dim3(HID / 32, HID / 32), blk>>>(out_w, woutT, HID, HID);
        transpose_h_kernel<<<dim3(H4 / 32, HID / 32), blk>>>(fc1_w, w1T, HID, H4);
        transpose_h_kernel<<<dim3(HID / 32, H4 / 32), blk>>>(fc2_w, w2T, H4, HID);
    }

    // 1. LayerNorm -> fp16
    ln_kernel<<<ROWS, 256>>>(hidden, ln_w, ln_b, ln);

    // 2. QKV + FC1 merged (both read ln)
    gemm_qkv_fc1<<<dim3(H3 / 128 + H4 / 128, ROWS / 128), 256, G_SMEM>>>(
        ln, wqkvT, w1T, qkv, fc1, qkv_b, fc1_b);

    // 3. RoPE (in place)
    {
        int total = NB * SS * NH * 16;
        rope_kernel<<<(total + 255) / 256, 256>>>(qkv);
    }

    // 4. flash attention -> attn (fp16)
    flash_h<<<dim3(SS / FBQ, NB * NH), 256, FLASH_SMEM>>>(qkv, attn);

    // 5. out = hidden + attn@Wo + b_o + fc1@W2 + b_2   (dual-phase K)
    gemm_dual<<<dim3(HID / 128, ROWS / 128), 256, G_SMEM>>>(
        attn, woutT, fc1, w2T, hidden, out, out_b, fc2_b);
}

// round 10
// speedup vs baseline: 8.7563x; 1.1511x over previous
#include <cuda_runtime.h>
#include <cuda_fp16.h>
#include <math.h>
#include <stdint.h>

#define NB 2
#define SS 2048
#define NH 32
#define HS 80
#define HID 2560
#define H3 7680
#define H4 10240
#define ROWS (NB*SS)          // 4096

// ---------------- scratch (static device globals; no allocation) ----------------
__device__ __half g_ln[(long)ROWS * HID];
__device__ __half g_qkv[(long)ROWS * H3];
__device__ __half g_attn[(long)ROWS * HID];
__device__ __half g_fc1[(long)ROWS * H4];
__device__ float  g_res[(long)ROWS * HID];     // fp32: hidden + fc2 + biases
__device__ float  g_bsum[HID];                 // out_b + fc2_b
// transposed fp16 weights: WT[n][k] = half(W[k][n])
__device__ __half g_wqkv_t[(long)H3 * HID];
__device__ __half g_wout_t[(long)HID * HID];
__device__ __half g_w1_t[(long)H4 * HID];
__device__ __half g_w2_t[(long)HID * H4];

// ---------------- small helpers ----------------
__device__ __forceinline__ float fast_gelu(float x) {
    const float c = 0.7978845608028654f;
    float x3 = x * x * x;
    return 0.5f * x * (1.0f + tanhf(c * (x + 0.044715f * x3)));
}

__device__ __forceinline__ uint32_t smem_u32(const void* p) {
    uint32_t a;
    asm("{ .reg .u64 t; cvta.to.shared.u64 t, %1; cvt.u32.u64 %0, t; }" : "=r"(a) : "l"(p));
    return a;
}

__device__ __forceinline__ void cp16(uint32_t dst, const void* src) {
    asm volatile("cp.async.cg.shared.global [%0], [%1], 16;" :: "r"(dst), "l"(src));
}
#define CP_COMMIT() asm volatile("cp.async.commit_group;" ::: "memory")
#define CP_WAIT1()  asm volatile("cp.async.wait_group 1;" ::: "memory")
#define CP_WAIT2()  asm volatile("cp.async.wait_group 2;" ::: "memory")

__device__ __forceinline__ void mma_f16(float* d, const uint32_t* a, uint32_t b0, uint32_t b1) {
    asm volatile("mma.sync.aligned.m16n8k16.row.col.f32.f16.f16.f32 "
        "{%0,%1,%2,%3}, {%4,%5,%6,%7}, {%8,%9}, {%0,%1,%2,%3};"
        : "+f"(d[0]), "+f"(d[1]), "+f"(d[2]), "+f"(d[3])
        : "r"(a[0]), "r"(a[1]), "r"(a[2]), "r"(a[3]), "r"(b0), "r"(b1));
}

__device__ __forceinline__ void ldsm_x4(uint32_t* r, uint32_t addr) {
    asm volatile("ldmatrix.sync.aligned.m8n8.x4.shared.b16 {%0,%1,%2,%3}, [%4];"
        : "=r"(r[0]), "=r"(r[1]), "=r"(r[2]), "=r"(r[3]) : "r"(addr));
}
__device__ __forceinline__ void ldsm_x2_trans(uint32_t& r0, uint32_t& r1, uint32_t addr) {
    asm volatile("ldmatrix.sync.aligned.m8n8.x2.trans.shared.b16 {%0,%1}, [%2];"
        : "=r"(r0), "=r"(r1) : "r"(addr));
}

__device__ __forceinline__ uint32_t packh2(float a, float b) {
    __half2 h = __floats2half2_rn(a, b);
    return *reinterpret_cast<uint32_t*>(&h);
}

// ---------------- block reduce ----------------
__device__ __forceinline__ float block_reduce_sum(float v, float* sh) {
    #pragma unroll
    for (int o = 16; o > 0; o >>= 1) v += __shfl_xor_sync(0xffffffffu, v, o);
    int wid = threadIdx.x >> 5;
    if ((threadIdx.x & 31) == 0) sh[wid] = v;
    __syncthreads();
    if (threadIdx.x < 32) {
        float t = (threadIdx.x < 8) ? sh[threadIdx.x] : 0.0f;
        #pragma unroll
        for (int o = 4; o > 0; o >>= 1) t += __shfl_xor_sync(0xffffffffu, t, o);
        if (threadIdx.x == 0) sh[0] = t;
    }
    __syncthreads();
    float r = sh[0];
    __syncthreads();
    return r;
}

// ---------------- LayerNorm (fp16 output) ----------------
__global__ void ln_kernel(const float* __restrict__ x,
                          const float* __restrict__ w,
                          const float* __restrict__ b,
                          __half* __restrict__ y) {
    __shared__ float sh[8];
    long row = blockIdx.x;
    const float* xr = x + row * HID;
    __half* yr = y + row * HID;
    float vals[10];
    float sum = 0.0f;
    #pragma unroll
    for (int i = 0; i < 10; i++) { vals[i] = xr[threadIdx.x + i * 256]; sum += vals[i]; }
    float mean = block_reduce_sum(sum, sh) * (1.0f / HID);
    float sq = 0.0f;
    #pragma unroll
    for (int i = 0; i < 10; i++) { float d = vals[i] - mean; sq += d * d; }
    float var = block_reduce_sum(sq, sh) * (1.0f / HID);
    float inv = rsqrtf(var + 1e-5f);
    #pragma unroll
    for (int i = 0; i < 10; i++) {
        int idx = threadIdx.x + i * 256;
        yr[idx] = __float2half_rn((vals[i] - mean) * inv * w[idx] + b[idx]);
    }
}

// ---------------- weight transpose + fp16: WT[n][k] = half(W[k][n]) ----------------
__global__ void transpose_h_kernel(const float* __restrict__ W, __half* __restrict__ WT,
                                   int K, int N) {
    __shared__ float t[32][33];
    int k0 = blockIdx.y * 32, n0 = blockIdx.x * 32;
    int x = threadIdx.x, y = threadIdx.y;   // 32 x 8
    #pragma unroll
    for (int i = 0; i < 32; i += 8)
        t[y + i][x] = W[(long)(k0 + y + i) * N + n0 + x];
    __syncthreads();
    #pragma unroll
    for (int i = 0; i < 32; i += 8)
        WT[(long)(n0 + y + i) * K + k0 + x] = __float2half_rn(t[x][y + i]);
}

// ---------------- bias sum: g_bsum = out_b + fc2_b ----------------
__global__ void bias_sum_kernel(const float* __restrict__ a, const float* __restrict__ b,
                                float* __restrict__ c) {
    int i = blockIdx.x * 256 + threadIdx.x;
    if (i < HID) c[i] = a[i] + b[i];
}

// ================= fp16 mma GEMM infrastructure =================
#define GSTAGES 4
#define GPITCH 40
#define GSTAGE (128 * GPITCH)                     // halves per operand-stage
#define G_SMEM (GSTAGES * 2 * GSTAGE * 2)         // 81920 bytes

// compute one BK=32 step from smem stage into acc[4][4][4]; A and B both via ldmatrix
__device__ __forceinline__ void gemm_compute_stage(
    const __half* as_s, const __half* bs_s,
    int m_off, int n_off, int lane,
    float acc[4][4][4]) {
    int bi = lane >> 3, br = lane & 7;   // ldsm matrix index / row within matrix
    #pragma unroll
    for (int ks = 0; ks < 2; ks++) {
        uint32_t af[4][4];
        #pragma unroll
        for (int mt = 0; mt < 4; mt++) {
            uint32_t addr = smem_u32(as_s + (m_off + 16 * mt + (lane & 15)) * GPITCH
                                          + ks * 16 + (lane >> 4) * 8);
            ldsm_x4(af[mt], addr);
        }
        // B: 2 x ldsm_x4; matrices: (nt_local = bi>>1, koff = 8*(bi&1))
        uint32_t bf[2][4];
        #pragma unroll
        for (int p = 0; p < 2; p++) {
            uint32_t addr = smem_u32(bs_s + (n_off + p * 16 + 8 * (bi >> 1) + br) * GPITCH
                                          + ks * 16 + 8 * (bi & 1));
            ldsm_x4(bf[p], addr);
        }
        #pragma unroll
        for (int mt = 0; mt < 4; mt++)
            #pragma unroll
            for (int nt = 0; nt < 4; nt++)
                mma_f16(acc[mt][nt], af[mt],
                        bf[nt >> 1][(nt & 1) * 2], bf[nt >> 1][(nt & 1) * 2 + 1]);
    }
}

// ---------------- merged QKV + FC1 GEMM (both read ln, K=HID) ----------------
__global__ __launch_bounds__(256, 2)
void gemm_qkv_fc1(const __half* __restrict__ ln,
                  const __half* __restrict__ wqkvT, const __half* __restrict__ w1T,
                  __half* __restrict__ qkv, __half* __restrict__ fc1,
                  const float* __restrict__ qkv_b, const float* __restrict__ fc1_b) {
    extern __shared__ __half hs[];
    __half* As = hs;
    __half* Bs = hs + GSTAGES * GSTAGE;

    int tid = threadIdx.x;
    int wid = tid >> 5, lane = tid & 31;
    int gid = lane >> 2, tig = lane & 3;
    int m_off = (wid >> 2) * 64;
    int n_off = (wid & 3) * 32;

    int bx = blockIdx.x;
    bool is_fc1 = bx >= (H3 / 128);
    int nb = is_fc1 ? bx - H3 / 128 : bx;
    const __half* Bb = is_fc1 ? (w1T + (long)nb * 128 * HID)
                              : (wqkvT + (long)nb * 128 * HID);
    const __half* Ab = ln + (long)blockIdx.y * 128 * HID;
    uint32_t as_u = smem_u32(As), bs_u = smem_u32(Bs);

    int lr = tid >> 2;
    int lc = (tid & 3) * 8;

    float acc[4][4][4];
    #pragma unroll
    for (int i = 0; i < 4; i++)
        #pragma unroll
        for (int j = 0; j < 4; j++)
            #pragma unroll
            for (int k = 0; k < 4; k++) acc[i][j][k] = 0.0f;

    const int iters = HID / 32;   // 80

    #pragma unroll
    for (int s = 0; s < 3; s++) {
        uint32_t off = (uint32_t)(s * GSTAGE + lr * GPITCH + lc) * 2u;
        cp16(as_u + off, Ab + (long)lr * HID + s * 32 + lc);
        cp16(bs_u + off, Bb + (long)lr * HID + s * 32 + lc);
        off += 64u * GPITCH * 2u;
        cp16(as_u + off, Ab + (long)(lr + 64) * HID + s * 32 + lc);
        cp16(bs_u + off, Bb + (long)(lr + 64) * HID + s * 32 + lc);
        CP_COMMIT();
    }

    for (int it = 0; it < iters; ++it) {
        CP_WAIT2();
        __syncthreads();
        int lt = it + 3;
        if (lt < iters) {
            int s = lt & 3;
            uint32_t off = (uint32_t)(s * GSTAGE + lr * GPITCH + lc) * 2u;
            cp16(as_u + off, Ab + (long)lr * HID + lt * 32 + lc);
            cp16(bs_u + off, Bb + (long)lr * HID + lt * 32 + lc);
            off += 64u * GPITCH * 2u;
            cp16(as_u + off, Ab + (long)(lr + 64) * HID + lt * 32 + lc);
            cp16(bs_u + off, Bb + (long)(lr + 64) * HID + lt * 32 + lc);
        }
        CP_COMMIT();
        gemm_compute_stage(As + (it & 3) * GSTAGE, Bs + (it & 3) * GSTAGE,
                           m_off, n_off, lane, acc);
    }

    const float* bias = is_fc1 ? fc1_b : qkv_b;
    int ldc = is_fc1 ? H4 : H3;
    __half* C = is_fc1 ? fc1 : qkv;
    #pragma unroll
    for (int mt = 0; mt < 4; mt++) {
        #pragma unroll
        for (int h2 = 0; h2 < 2; h2++) {
            long m = (long)blockIdx.y * 128 + m_off + 16 * mt + gid + h2 * 8;
            #pragma unroll
            for (int nt = 0; nt < 4; nt++) {
                int n = nb * 128 + n_off + 8 * nt + 2 * tig;
                float2 bv = *(const float2*)(bias + n);
                float v0 = acc[mt][nt][2 * h2 + 0] + bv.x;
                float v1 = acc[mt][nt][2 * h2 + 1] + bv.y;
                if (is_fc1) { v0 = fast_gelu(v0); v1 = fast_gelu(v1); }
                *(__half2*)(C + m * ldc + n) = __floats2half2_rn(v0, v1);
            }
        }
    }
}

// ---------------- generic fp32-accumulating GEMM: C = R + A@B^T (+bias) ----------------
// HAS_BIAS: fc2 phase (R=hidden, bias=bsum, C=g_res). !HAS_BIAS: outproj (R=g_res, C=out).
template<bool HAS_BIAS>
__global__ __launch_bounds__(256, 2)
void gemm_addf32(const __half* __restrict__ A, int lda,
                 const __half* __restrict__ B, int ldb,
                 int K,
                 const float* __restrict__ R, const float* __restrict__ bias,
                 float* __restrict__ C) {
    extern __shared__ __half hs[];
    __half* As = hs;
    __half* Bs = hs + GSTAGES * GSTAGE;

    int tid = threadIdx.x;
    int wid = tid >> 5, lane = tid & 31;
    int gid = lane >> 2, tig = lane & 3;
    int m_off = (wid >> 2) * 64;
    int n_off = (wid & 3) * 32;

    const __half* Ab = A + (long)blockIdx.y * 128 * lda;
    const __half* Bb = B + (long)blockIdx.x * 128 * ldb;
    uint32_t as_u = smem_u32(As), bs_u = smem_u32(Bs);

    int lr = tid >> 2;
    int lc = (tid & 3) * 8;

    float acc[4][4][4];
    #pragma unroll
    for (int i = 0; i < 4; i++)
        #pragma unroll
        for (int j = 0; j < 4; j++)
            #pragma unroll
            for (int k = 0; k < 4; k++) acc[i][j][k] = 0.0f;

    int iters = K / 32;

    #pragma unroll
    for (int s = 0; s < 3; s++) {
        uint32_t off = (uint32_t)(s * GSTAGE + lr * GPITCH + lc) * 2u;
        cp16(as_u + off, Ab + (long)lr * lda + s * 32 + lc);
        cp16(bs_u + off, Bb + (long)lr * ldb + s * 32 + lc);
        off += 64u * GPITCH * 2u;
        cp16(as_u + off, Ab + (long)(lr + 64) * lda + s * 32 + lc);
        cp16(bs_u + off, Bb + (long)(lr + 64) * ldb + s * 32 + lc);
        CP_COMMIT();
    }

    for (int it = 0; it < iters; ++it) {
        CP_WAIT2();
        __syncthreads();
        int lt = it + 3;
        if (lt < iters) {
            int s = lt & 3;
            uint32_t off = (uint32_t)(s * GSTAGE + lr * GPITCH + lc) * 2u;
            cp16(as_u + off, Ab + (long)lr * lda + lt * 32 + lc);
            cp16(bs_u + off, Bb + (long)lr * ldb + lt * 32 + lc);
            off += 64u * GPITCH * 2u;
            cp16(as_u + off, Ab + (long)(lr + 64) * lda + lt * 32 + lc);
            cp16(bs_u + off, Bb + (long)(lr + 64) * ldb + lt * 32 + lc);
        }
        CP_COMMIT();
        gemm_compute_stage(As + (it & 3) * GSTAGE, Bs + (it & 3) * GSTAGE,
                           m_off, n_off, lane, acc);
    }

    #pragma unroll
    for (int mt = 0; mt < 4; mt++) {
        #pragma unroll
        for (int h2 = 0; h2 < 2; h2++) {
            long m = (long)blockIdx.y * 128 + m_off + 16 * mt + gid + h2 * 8;
            #pragma unroll
            for (int nt = 0; nt < 4; nt++) {
                int n = blockIdx.x * 128 + n_off + 8 * nt + 2 * tig;
                float2 r = *(const float2*)(R + m * HID + n);
                float v0 = acc[mt][nt][2 * h2 + 0] + r.x;
                float v1 = acc[mt][nt][2 * h2 + 1] + r.y;
                if (HAS_BIAS) {
                    float2 bv = *(const float2*)(bias + n);
                    v0 += bv.x; v1 += bv.y;
                }
                *(float2*)(C + m * HID + n) = make_float2(v0, v1);
            }
        }
    }
}

// ---------------- partial RoPE (in-place on fp16 q,k) ----------------
__global__ void rope_kernel(__half* __restrict__ qkv) {
    int idx = blockIdx.x * blockDim.x + threadIdx.x;
    const int total = NB * SS * NH * 16;
    if (idx >= total) return;
    int p = idx & 15;
    int h = (idx >> 4) & 31;
    int s = (idx >> 9) & (SS - 1);
    int b = idx >> 20;
    float inv = __expf(-(float)p * (9.210340371976184f / 16.0f));
    float angle = (float)s * inv;
    float sn, cs;
    sincosf(angle, &sn, &cs);
    long base = ((long)b * SS + s) * H3 + (long)h * HS;
    __half* qp = qkv + base;
    __half* kp = qkv + base + HID;
    float q1 = __half2float(qp[p]), q2 = __half2float(qp[p + 16]);
    qp[p]      = __float2half_rn(q1 * cs - q2 * sn);
    qp[p + 16] = __float2half_rn(q1 * sn + q2 * cs);
    float k1 = __half2float(kp[p]), k2 = __half2float(kp[p + 16]);
    kp[p]      = __float2half_rn(k1 * cs - k2 * sn);
    kp[p + 16] = __float2half_rn(k1 * sn + k2 * cs);
}

// ================= fp16 flash attention (3-stage, single sync/iter) =================
#define FBQ 128
#define FBK 64
#define KVP 88
#define FSTAGE (FBK * KVP)
#define FLASH_SMEM (3 * 2 * FSTAGE * 2)          // 67584 bytes

__global__ __launch_bounds__(256, 1)
void flash_h(const __half* __restrict__ qkv, __half* __restrict__ attn) {
    extern __shared__ __half fs[];
    __half* Ks = fs;
    __half* Vs = fs + 3 * FSTAGE;

    int tid = threadIdx.x, wid = tid >> 5, lane = tid & 31;
    int gid = lane >> 2, tig = lane & 3;
    int qt = (int)gridDim.x - 1 - blockIdx.x;
    int q0 = qt * FBQ;
    int b = blockIdx.y >> 5, h = blockIdx.y & 31;
    int m0 = wid * 16;

    const __half* qbase = qkv + (long)b * SS * H3 + (long)h * HS;
    const __half* kbase = qbase + HID;
    const __half* vbase = qbase + 2 * HID;

    int row0 = q0 + m0 + gid;
    int row1 = row0 + 8;

    uint32_t qf[5][4];
    {
        const __half* q0p = qbase + (long)row0 * H3;
        const __half* q1p = qbase + (long)row1 * H3;
        #pragma unroll
        for (int g = 0; g < 5; g++) {
            qf[g][0] = *(const uint32_t*)(q0p + 16 * g + 2 * tig);
            qf[g][1] = *(const uint32_t*)(q1p + 16 * g + 2 * tig);
            qf[g][2] = *(const uint32_t*)(q0p + 16 * g + 8 + 2 * tig);
            qf[g][3] = *(const uint32_t*)(q1p + 16 * g + 8 + 2 * tig);
        }
    }

    float oacc[10][4];
    #pragma unroll
    for (int i = 0; i < 10; i++)
        #pragma unroll
        for (int j = 0; j < 4; j++) oacc[i][j] = 0.0f;
    float mrow0 = -1e30f, mrow1 = -1e30f, lrow0 = 0.0f, lrow1 = 0.0f;

    int ntiles = q0 / FBK + 2;
    uint32_t ks_u = smem_u32(Ks), vs_u = smem_u32(Vs);

    auto issue_tile = [&](int t, int stage) {
        int kv = t * FBK;
        #pragma unroll
        for (int i = 0; i < 3; i++) {
            int c = tid + i * 256;
            if (c < 640) {
                int r = c / 10, cc = c % 10;
                uint32_t off = (uint32_t)((stage * FBK + r) * KVP + cc * 8) * 2u;
                cp16(ks_u + off, kbase + (long)(kv + r) * H3 + cc * 8);
                cp16(vs_u + off, vbase + (long)(kv + r) * H3 + cc * 8);
            }
        }
    };

    issue_tile(0, 0); CP_COMMIT();
    issue_tile(1, 1); CP_COMMIT();

    const float scale = 0.11180339887498949f;

    for (int t = 0; t < ntiles; ++t) {
        CP_WAIT1();
        __syncthreads();
        if (t + 2 < ntiles) issue_tile(t + 2, (t + 2) % 3);
        CP_COMMIT();
        int stage = t % 3;

        float sacc[8][4];
        #pragma unroll
        for (int i = 0; i < 8; i++)
            #pragma unroll
            for (int j = 0; j < 4; j++) sacc[i][j] = 0.0f;

        const __half* kt = Ks + stage * FSTAGE;
        #pragma unroll
        for (int nt = 0; nt < 8; nt++) {
            const uint32_t* bp = (const uint32_t*)(kt + (8 * nt + gid) * KVP);
            #pragma unroll
            for (int g = 0; g < 5; g++)
                mma_f16(sacc[nt], qf[g], bp[8 * g + tig], bp[8 * g + 4 + tig]);
        }

        int kv0 = t * FBK;
        bool need_mask = (t >= ntiles - 2);
        #pragma unroll
        for (int nt = 0; nt < 8; nt++) {
            int c0 = kv0 + nt * 8 + 2 * tig;
            #pragma unroll
            for (int j = 0; j < 4; j++) sacc[nt][j] *= scale;
            if (need_mask) {
                if (c0 > row0)     sacc[nt][0] = -1e30f;
                if (c0 + 1 > row0) sacc[nt][1] = -1e30f;
                if (c0 > row1)     sacc[nt][2] = -1e30f;
                if (c0 + 1 > row1) sacc[nt][3] = -1e30f;
            }
        }

        float rm0 = -1e30f, rm1 = -1e30f;
        #pragma unroll
        for (int nt = 0; nt < 8; nt++) {
            rm0 = fmaxf(rm0, fmaxf(sacc[nt][0], sacc[nt][1]));
            rm1 = fmaxf(rm1, fmaxf(sacc[nt][2], sacc[nt][3]));
        }
        rm0 = fmaxf(rm0, __shfl_xor_sync(0xffffffffu, rm0, 1));
        rm0 = fmaxf(rm0, __shfl_xor_sync(0xffffffffu, rm0, 2));
        rm1 = fmaxf(rm1, __shfl_xor_sync(0xffffffffu, rm1, 1));
        rm1 = fmaxf(rm1, __shfl_xor_sync(0xffffffffu, rm1, 2));
        float mn0 = fmaxf(mrow0, rm0);
        float mn1 = fmaxf(mrow1, rm1);

        float rs0 = 0.0f, rs1 = 0.0f;
        uint32_t ph[8][2];
        #pragma unroll
        for (int nt = 0; nt < 8; nt++) {
            float p0 = __expf(sacc[nt][0] - mn0);
            float p1 = __expf(sacc[nt][1] - mn0);
            float p2 = __expf(sacc[nt][2] - mn1);
            float p3 = __expf(sacc[nt][3] - mn1);
            rs0 += p0 + p1;
            rs1 += p2 + p3;
            ph[nt][0] = packh2(p0, p1);
            ph[nt][1] = packh2(p2, p3);
        }
        rs0 += __shfl_xor_sync(0xffffffffu, rs0, 1);
        rs0 += __shfl_xor_sync(0xffffffffu, rs0, 2);
        rs1 += __shfl_xor_sync(0xffffffffu, rs1, 1);
        rs1 += __shfl_xor_sync(0xffffffffu, rs1, 2);

        float a0 = __expf(mrow0 - mn0);
        float a1 = __expf(mrow1 - mn1);
        lrow0 = lrow0 * a0 + rs0;
        lrow1 = lrow1 * a1 + rs1;
        mrow0 = mn0; mrow1 = mn1;
        #pragma unroll
        for (int nt = 0; nt < 10; nt++) {
            oacc[nt][0] *= a0; oacc[nt][1] *= a0;
            oacc[nt][2] *= a1; oacc[nt][3] *= a1;
        }

        const __half* vt = Vs + stage * FSTAGE;
        #pragma unroll
        for (int g = 0; g < 4; g++) {
            uint32_t af[4] = { ph[2 * g][0], ph[2 * g][1], ph[2 * g + 1][0], ph[2 * g + 1][1] };
            #pragma unroll
            for (int nt = 0; nt < 10; nt++) {
                uint32_t b0, b1;
                uint32_t addr = smem_u32(vt + (16 * g + (lane & 15)) * KVP + nt * 8);
                ldsm_x2_trans(b0, b1, addr);
                mma_f16(oacc[nt], af, b0, b1);
            }
        }
    }

    float inv0 = 1.0f / lrow0;
    float inv1 = 1.0f / lrow1;
    __half* o0 = attn + ((long)b * SS + row0) * HID + h * HS;
    __half* o1 = attn + ((long)b * SS + row1) * HID + h * HS;
    #pragma unroll
    for (int nt = 0; nt < 10; nt++) {
        int cc = nt * 8 + 2 * tig;
        *(__half2*)(o0 + cc) = __floats2half2_rn(oacc[nt][0] * inv0, oacc[nt][1] * inv0);
        *(__half2*)(o1 + cc) = __floats2half2_rn(oacc[nt][2] * inv1, oacc[nt][3] * inv1);
    }
}

// ---------------- host-side launcher ----------------
static void* sym_addr(const void* symbol) {
    void* p = nullptr;
    cudaGetSymbolAddress(&p, symbol);
    return p;
}

extern "C" void kernel_launch(void* const* d_in, const int* in_sizes, int n_in,
                              void* d_out, int out_size) {
    const float* hidden = (const float*)d_in[0];
    const float* ln_w   = (const float*)d_in[1];
    const float* ln_b   = (const float*)d_in[2];
    const float* qkv_w  = (const float*)d_in[3];
    const float* qkv_b  = (const float*)d_in[4];
    const float* out_w  = (const float*)d_in[5];
    const float* out_b  = (const float*)d_in[6];
    const float* fc1_w  = (const float*)d_in[7];
    const float* fc1_b  = (const float*)d_in[8];
    const float* fc2_w  = (const float*)d_in[9];
    const float* fc2_b  = (const float*)d_in[10];
    float* out = (float*)d_out;

    __half* ln    = (__half*)sym_addr(g_ln);
    __half* qkv   = (__half*)sym_addr(g_qkv);
    __half* attn  = (__half*)sym_addr(g_attn);
    __half* fc1   = (__half*)sym_addr(g_fc1);
    float*  res   = (float*)sym_addr(g_res);
    float*  bsum  = (float*)sym_addr(g_bsum);
    __half* wqkvT = (__half*)sym_addr(g_wqkv_t);
    __half* woutT = (__half*)sym_addr(g_wout_t);
    __half* w1T   = (__half*)sym_addr(g_w1_t);
    __half* w2T   = (__half*)sym_addr(g_w2_t);

    cudaFuncSetAttribute(gemm_qkv_fc1, cudaFuncAttributeMaxDynamicSharedMemorySize, G_SMEM);
    cudaFuncSetAttribute(gemm_addf32<true>, cudaFuncAttributeMaxDynamicSharedMemorySize, G_SMEM);
    cudaFuncSetAttribute(gemm_addf32<false>, cudaFuncAttributeMaxDynamicSharedMemorySize, G_SMEM);
    cudaFuncSetAttribute(flash_h, cudaFuncAttributeMaxDynamicSharedMemorySize, FLASH_SMEM);

    // fork resources (created per call; host-side objects only, never destroyed
    // to stay capture-safe — kernel_launch runs twice total)
    cudaStream_t s2;
    cudaStreamCreateWithFlags(&s2, cudaStreamNonBlocking);
    cudaEvent_t ev1, ev2;
    cudaEventCreateWithFlags(&ev1, cudaEventDisableTiming);
    cudaEventCreateWithFlags(&ev2, cudaEventDisableTiming);

    // 0. transpose weights to fp16 [N,K]; combined bias
    {
        dim3 blk(32, 8);
        transpose_h_kernel<<<dim3(H3 / 32, HID / 32), blk>>>(qkv_w, wqkvT, HID, H3);
        transpose_h_kernel<<<dim3(HID / 32, HID / 32), blk>>>(out_w, woutT, HID, HID);
        transpose_h_kernel<<<dim3(H4 / 32, HID / 32), blk>>>(fc1_w, w1T, HID, H4);
        transpose_h_kernel<<<dim3(HID / 32, H4 / 32), blk>>>(fc2_w, w2T, H4, HID);
        bias_sum_kernel<<<(HID + 255) / 256, 256>>>(out_b, fc2_b, bsum);
    }

    // 1. LayerNorm -> fp16
    ln_kernel<<<ROWS, 256>>>(hidden, ln_w, ln_b, ln);

    // 2. QKV + FC1 merged
    gemm_qkv_fc1<<<dim3(H3 / 128 + H4 / 128, ROWS / 128), 256, G_SMEM>>>(
        ln, wqkvT, w1T, qkv, fc1, qkv_b, fc1_b);

    // fork: fc2 (side stream) overlaps rope + flash (main stream)
    cudaEventRecord(ev1, 0);
    cudaStreamWaitEvent(s2, ev1, 0);

    // side: res = hidden + fc1@W2 + (b2 + b_o)
    gemm_addf32<true><<<dim3(HID / 128, ROWS / 128), 256, G_SMEM, s2>>>(
        fc1, H4, w2T, H4, H4, hidden, bsum, res);
    cudaEventRecord(ev2, s2);

    // main: rope + flash
    {
        int total = NB * SS * NH * 16;
        rope_kernel<<<(total + 255) / 256, 256>>>(qkv);
    }
    flash_h<<<dim3(SS / FBQ, NB * NH), 256, FLASH_SMEM>>>(qkv, attn);

    // join, then out = res + attn@Wo
    cudaStreamWaitEvent(0, ev2, 0);
    gemm_addf32<false><<<dim3(HID / 128, ROWS / 128), 256, G_SMEM>>>(
        attn, HID, woutT, HID, HID, res, nullptr, out);
}